// round 14
// baseline (speedup 1.0000x reference)
#include <cuda_runtime.h>
#include <cuda_bf16.h>
#include <math.h>
#include <stdint.h>

// ---------------- problem dims ----------------
#define S_DIM 4096
#define B_DIM 2
#define E_DIM 1024
#define H_DIM 8
#define R_DIM 2
#define C_DIM 64
#define D_DIM 128
#define NC_DIM 64                    // S / C
#define NSEG (B_DIM*R_DIM*H_DIM)     // 32
#define MROWS (S_DIM*B_DIM)          // 8192
#define SCALE_F 0.08838834764831845f // D^-0.5
#define NEG_F (-1e9f)
#define NEG_SELF_F (-1e5f)

// ---------------- scratch (device globals; no allocation) ----------------
__device__ float g_qraw[MROWS*E_DIM];     // x@wq^T + bq (fp32, feeds hash)
__device__ float g_oout[NSEG*S_DIM*D_DIM];
__device__ float g_olse[NSEG*S_DIM];
__device__ int   g_hash[NSEG*S_DIM];
__device__ int   g_sidx[NSEG*S_DIM];
__device__ int   g_shash[NSEG*S_DIM];
// pre-split bf16 hi/lo (u32 = bf16x2 pairs along last dim)
__device__ uint32_t g_xh[MROWS*E_DIM/2], g_xl[MROWS*E_DIM/2];
__device__ uint32_t g_wvh[E_DIM*E_DIM/2], g_wvl[E_DIM*E_DIM/2];
__device__ uint32_t g_woh[E_DIM*E_DIM/2], g_wol[E_DIM*E_DIM/2];
__device__ uint32_t g_och[MROWS*E_DIM/2], g_ocl[MROWS*E_DIM/2]; // combined o
__device__ uint32_t g_qsh[MROWS*E_DIM/2], g_qsl[MROWS*E_DIM/2]; // scaled q
__device__ uint32_t g_kbh[MROWS*E_DIM/2], g_kbl[MROWS*E_DIM/2]; // normalized k
__device__ uint32_t g_vbh[MROWS*E_DIM/2], g_vbl[MROWS*E_DIM/2]; // v (pre-split)

// ---------------- bf16 split helpers ----------------
__device__ __forceinline__ void split2(float a, float b, uint32_t& h, uint32_t& l) {
    __nv_bfloat162 hh = __floats2bfloat162_rn(a, b);
    h = *reinterpret_cast<uint32_t*>(&hh);
    __nv_bfloat162 ll = __floats2bfloat162_rn(a - __bfloat162float(hh.x),
                                              b - __bfloat162float(hh.y));
    l = *reinterpret_cast<uint32_t*>(&ll);
}

__device__ __forceinline__ void mma_bf16(float* d, const uint32_t* a,
                                         const uint32_t* b) {
    asm volatile(
        "mma.sync.aligned.m16n8k16.row.col.f32.bf16.bf16.f32 "
        "{%0,%1,%2,%3}, {%4,%5,%6,%7}, {%8,%9}, {%0,%1,%2,%3};\n"
        : "+f"(d[0]), "+f"(d[1]), "+f"(d[2]), "+f"(d[3])
        : "r"(a[0]), "r"(a[1]), "r"(a[2]), "r"(a[3]), "r"(b[0]), "r"(b[1]));
}

__device__ __forceinline__ uint32_t prmt(uint32_t a, uint32_t b, uint32_t sel) {
    uint32_t r;
    asm("prmt.b32 %0, %1, %2, %3;" : "=r"(r) : "r"(a), "r"(b), "r"(sel));
    return r;
}

// ---------------- merged split conversion kernel (memory-bound) --------
#define N4X (MROWS*E_DIM/4)
#define N4W (E_DIM*E_DIM/4)
__global__ void split_all_kernel(const float4* __restrict__ x,
                                 const float4* __restrict__ wv,
                                 const float4* __restrict__ wo)
{
    int i = blockIdx.x * 256 + threadIdx.x;
    const float4* src; uint2 *dh, *dl; int j;
    if (i < N4X) {
        src = x; dh = (uint2*)g_xh; dl = (uint2*)g_xl; j = i;
    } else if (i < N4X + N4W) {
        src = wv; dh = (uint2*)g_wvh; dl = (uint2*)g_wvl; j = i - N4X;
    } else {
        src = wo; dh = (uint2*)g_woh; dl = (uint2*)g_wol; j = i - N4X - N4W;
    }
    float4 v = src[j];
    uint2 h, l;
    split2(v.x, v.y, h.x, l.x);
    split2(v.z, v.w, h.y, l.y);
    dh[j] = h; dl[j] = l;
}

// =====================================================================
// SIMT fp32 GEMM (q projection — flip-free path).
// =====================================================================
__global__ void __launch_bounds__(256)
gemm_bias_kernel(const float* __restrict__ A, const float* __restrict__ W,
                 const float* __restrict__ bias, float* __restrict__ C)
{
    __shared__ float As[2][16][132];
    __shared__ float Ws[2][16][132];
    const int K = E_DIM, N = E_DIM;

    const int tid = threadIdx.x;
    const int bm = blockIdx.y * 128;
    const int bn = blockIdx.x * 128;
    const int tm = tid >> 4;
    const int tn = tid & 15;

    float acc[8][8];
#pragma unroll
    for (int i = 0; i < 8; i++)
#pragma unroll
        for (int j = 0; j < 8; j++) acc[i][j] = 0.f;

    float4 ha[2], hw[2];

#define GLD(k0)                                                            \
    {                                                                      \
        _Pragma("unroll")                                                  \
        for (int it = 0; it < 2; it++) {                                   \
            int l = it * 256 + tid; int m = l >> 2; int kq = (l & 3) * 4;  \
            ha[it] = *(const float4*)&A[(size_t)(bm + m) * K + (k0) + kq]; \
            hw[it] = *(const float4*)&W[(size_t)(bn + m) * K + (k0) + kq]; \
        }                                                                  \
    }
#define GST(nb)                                                            \
    {                                                                      \
        _Pragma("unroll")                                                  \
        for (int it = 0; it < 2; it++) {                                   \
            int l = it * 256 + tid; int m = l >> 2; int kq = (l & 3) * 4;  \
            As[nb][kq + 0][m] = ha[it].x; As[nb][kq + 1][m] = ha[it].y;    \
            As[nb][kq + 2][m] = ha[it].z; As[nb][kq + 3][m] = ha[it].w;    \
            Ws[nb][kq + 0][m] = hw[it].x; Ws[nb][kq + 1][m] = hw[it].y;    \
            Ws[nb][kq + 2][m] = hw[it].z; Ws[nb][kq + 3][m] = hw[it].w;    \
        }                                                                  \
    }

    GLD(0); GST(0); __syncthreads();

    const int nIter = K >> 4;
    for (int ii = 0; ii < nIter; ii++) {
        if (ii + 1 < nIter) GLD((ii + 1) << 4);
        const int cb = ii & 1;
#pragma unroll
        for (int k = 0; k < 16; k++) {
            float4 a0 = *(const float4*)&As[cb][k][tm * 8];
            float4 a1 = *(const float4*)&As[cb][k][tm * 8 + 4];
            float4 b0 = *(const float4*)&Ws[cb][k][tn * 8];
            float4 b1 = *(const float4*)&Ws[cb][k][tn * 8 + 4];
            float av[8] = {a0.x, a0.y, a0.z, a0.w, a1.x, a1.y, a1.z, a1.w};
            float bv[8] = {b0.x, b0.y, b0.z, b0.w, b1.x, b1.y, b1.z, b1.w};
#pragma unroll
            for (int i = 0; i < 8; i++)
#pragma unroll
                for (int j = 0; j < 8; j++) acc[i][j] += av[i] * bv[j];
        }
        if (ii + 1 < nIter) GST((ii + 1) & 1);
        __syncthreads();
    }
#undef GLD
#undef GST

    float4 bb0 = *(const float4*)&bias[bn + tn * 8];
    float4 bb1 = *(const float4*)&bias[bn + tn * 8 + 4];
#pragma unroll
    for (int i = 0; i < 8; i++) {
        float4 o0, o1;
        o0.x = acc[i][0] + bb0.x; o0.y = acc[i][1] + bb0.y;
        o0.z = acc[i][2] + bb0.z; o0.w = acc[i][3] + bb0.w;
        o1.x = acc[i][4] + bb1.x; o1.y = acc[i][5] + bb1.y;
        o1.z = acc[i][6] + bb1.z; o1.w = acc[i][7] + bb1.w;
        size_t rowoff = (size_t)(bm + tm * 8 + i) * N + bn + tn * 8;
        *(float4*)&C[rowoff]     = o0;
        *(float4*)&C[rowoff + 4] = o1;
    }
}

// =====================================================================
// bf16 mma split GEMM with PRE-CONVERTED hi/lo inputs.
// OutSplit=true: write bf16 hi/lo (pairs along N) instead of fp32.
// =====================================================================
#define RS 20
#define BGEMM_SMEM (2 * 4 * 128 * RS * 4)   // 81920 B

template<bool OutSplit>
__global__ void __launch_bounds__(256, 2)
gemm_bf16_kernel(const uint32_t* __restrict__ Ah, const uint32_t* __restrict__ Al,
                 const uint32_t* __restrict__ Wh, const uint32_t* __restrict__ Wl,
                 const float* __restrict__ bias, float* __restrict__ C,
                 uint32_t* __restrict__ Uh, uint32_t* __restrict__ Ul)
{
    extern __shared__ uint32_t bsm[];
    uint32_t* base[2];
    base[0] = bsm;
    base[1] = bsm + 4 * 128 * RS;
    const int K = E_DIM, N = E_DIM, K2 = E_DIM / 2;

    const int tid = threadIdx.x;
    const int wid = tid >> 5, lane = tid & 31;
    const int g = lane >> 2, t = lane & 3;
    const int warp_m = wid & 1;
    const int warp_n = wid >> 1;
    const int bm = blockIdx.y * 128, bn = blockIdx.x * 128;

    float acc[4][4][4];
#pragma unroll
    for (int mi = 0; mi < 4; mi++)
#pragma unroll
        for (int ni = 0; ni < 4; ni++)
#pragma unroll
            for (int r = 0; r < 4; r++) acc[mi][ni][r] = 0.f;

    uint4 rah[2], ral[2], rwh[2], rwl[2];

#define BGLD(k02)                                                            \
    {                                                                        \
        _Pragma("unroll")                                                    \
        for (int it = 0; it < 2; it++) {                                     \
            int task = it * 256 + tid; int row = task >> 2; int q4 = task & 3;\
            size_t oa = (size_t)(bm + row) * K2 + (k02) + q4 * 4;            \
            size_t ow = (size_t)(bn + row) * K2 + (k02) + q4 * 4;            \
            rah[it] = *(const uint4*)&Ah[oa]; ral[it] = *(const uint4*)&Al[oa];\
            rwh[it] = *(const uint4*)&Wh[ow]; rwl[it] = *(const uint4*)&Wl[ow];\
        }                                                                    \
    }
#define BGST(nb)                                                             \
    {                                                                        \
        uint32_t* sAh = base[nb];                                            \
        uint32_t* sAl = sAh + 128 * RS;                                      \
        uint32_t* sBh = sAl + 128 * RS;                                      \
        uint32_t* sBl = sBh + 128 * RS;                                      \
        _Pragma("unroll")                                                    \
        for (int it = 0; it < 2; it++) {                                     \
            int task = it * 256 + tid; int row = task >> 2; int q4 = task & 3;\
            int off = row * RS + q4 * 4;                                     \
            *(uint4*)&sAh[off] = rah[it]; *(uint4*)&sAl[off] = ral[it];      \
            *(uint4*)&sBh[off] = rwh[it]; *(uint4*)&sBl[off] = rwl[it];      \
        }                                                                    \
    }

    BGLD(0); BGST(0); __syncthreads();

    const int nIter = K >> 5;
    for (int ii = 0; ii < nIter; ii++) {
        if (ii + 1 < nIter) BGLD((ii + 1) * 16);
        const uint32_t* Ahs = base[ii & 1];
        const uint32_t* Als = Ahs + 128 * RS;
        const uint32_t* Bhs = Als + 128 * RS;
        const uint32_t* Bls = Bhs + 128 * RS;

#pragma unroll
        for (int s = 0; s < 2; s++) {
            const int j0 = s * 8;
            uint32_t af[4][4], bh[4][2];
#pragma unroll
            for (int mi = 0; mi < 4; mi++) {
                int r0 = warp_m * 64 + mi * 16 + g;
                af[mi][0] = Ahs[r0 * RS + j0 + t];
                af[mi][1] = Ahs[(r0 + 8) * RS + j0 + t];
                af[mi][2] = Ahs[r0 * RS + j0 + 4 + t];
                af[mi][3] = Ahs[(r0 + 8) * RS + j0 + 4 + t];
            }
#pragma unroll
            for (int ni = 0; ni < 4; ni++) {
                int n0 = warp_n * 32 + ni * 8 + g;
                bh[ni][0] = Bhs[n0 * RS + j0 + t];
                bh[ni][1] = Bhs[n0 * RS + j0 + 4 + t];
            }
#pragma unroll
            for (int mi = 0; mi < 4; mi++)
#pragma unroll
                for (int ni = 0; ni < 4; ni++)
                    mma_bf16(acc[mi][ni], af[mi], bh[ni]);

            uint32_t bl[4][2];
#pragma unroll
            for (int ni = 0; ni < 4; ni++) {
                int n0 = warp_n * 32 + ni * 8 + g;
                bl[ni][0] = Bls[n0 * RS + j0 + t];
                bl[ni][1] = Bls[n0 * RS + j0 + 4 + t];
            }
#pragma unroll
            for (int mi = 0; mi < 4; mi++)
#pragma unroll
                for (int ni = 0; ni < 4; ni++)
                    mma_bf16(acc[mi][ni], af[mi], bl[ni]);

#pragma unroll
            for (int mi = 0; mi < 4; mi++) {
                int r0 = warp_m * 64 + mi * 16 + g;
                af[mi][0] = Als[r0 * RS + j0 + t];
                af[mi][1] = Als[(r0 + 8) * RS + j0 + t];
                af[mi][2] = Als[r0 * RS + j0 + 4 + t];
                af[mi][3] = Als[(r0 + 8) * RS + j0 + 4 + t];
            }
#pragma unroll
            for (int mi = 0; mi < 4; mi++)
#pragma unroll
                for (int ni = 0; ni < 4; ni++)
                    mma_bf16(acc[mi][ni], af[mi], bh[ni]);
        }
        if (ii + 1 < nIter) BGST((ii + 1) & 1);
        __syncthreads();
    }
#undef BGLD
#undef BGST

#pragma unroll
    for (int mi = 0; mi < 4; mi++) {
        int row0 = bm + warp_m * 64 + mi * 16 + g;
#pragma unroll
        for (int ni = 0; ni < 4; ni++) {
            int col = bn + warp_n * 32 + ni * 8 + 2 * t;
            float b0 = bias[col], b1 = bias[col + 1];
            float v00 = acc[mi][ni][0] + b0, v01 = acc[mi][ni][1] + b1;
            float v10 = acc[mi][ni][2] + b0, v11 = acc[mi][ni][3] + b1;
            if (OutSplit) {
                uint32_t hh, ll;
                size_t i0 = (size_t)row0 * (N / 2) + (col >> 1);
                split2(v00, v01, hh, ll);
                Uh[i0] = hh; Ul[i0] = ll;
                size_t i1 = (size_t)(row0 + 8) * (N / 2) + (col >> 1);
                split2(v10, v11, hh, ll);
                Uh[i1] = hh; Ul[i1] = ll;
            } else {
                *(float2*)&C[(size_t)row0 * N + col] = make_float2(v00, v01);
                *(float2*)&C[(size_t)(row0 + 8) * N + col] = make_float2(v10, v11);
            }
        }
    }
}

// ---------------- fused norm + split: k = q/||q|| and qs = q*SCALE ----
__global__ void norm_split_kernel()
{
    const int row = blockIdx.x;
    const int tid = threadIdx.x;      // 256
    const float4* q4 = (const float4*)(g_qraw + (size_t)row * E_DIM);
    float4 v = q4[tid];
    float ss = v.x * v.x + v.y * v.y + v.z * v.z + v.w * v.w;
#pragma unroll
    for (int o = 16; o > 0; o >>= 1) ss += __shfl_xor_sync(0xffffffffu, ss, o);
    __shared__ float red[8];
    __shared__ float s_inv;
    if ((tid & 31) == 0) red[tid >> 5] = ss;
    __syncthreads();
    if (tid == 0) {
        float tt = 0.f;
#pragma unroll
        for (int i = 0; i < 8; i++) tt += red[i];
        s_inv = 1.0f / sqrtf(tt);
    }
    __syncthreads();
    const float inv = s_inv;

    const int idx = row * 256 + tid;  // uint2 index
    uint2 h, l;
    split2(v.x * inv, v.y * inv, h.x, l.x);
    split2(v.z * inv, v.w * inv, h.y, l.y);
    ((uint2*)g_kbh)[idx] = h; ((uint2*)g_kbl)[idx] = l;
    split2(v.x * SCALE_F, v.y * SCALE_F, h.x, l.x);
    split2(v.z * SCALE_F, v.w * SCALE_F, h.y, l.y);
    ((uint2*)g_qsh)[idx] = h; ((uint2*)g_qsl)[idx] = l;
}

// ---------------- LSH hashing: both rounds fused ----------------------
__global__ void hash_kernel(const float* __restrict__ hash_w)
{
    const int bh = blockIdx.y;               // b*H + h
    const int b = bh / H_DIM;
    const int h = bh % H_DIM;

    __shared__ float hw[2][D_DIM * 8];
    for (int r = 0; r < 2; r++) {
        const float* hwp = hash_w + (size_t)(r * H_DIM + h) * D_DIM * 8;
        for (int i = threadIdx.x; i < D_DIM * 8; i += 256) hw[r][i] = hwp[i];
    }
    __syncthreads();

    const int s = blockIdx.x * 256 + threadIdx.x;
    const float4* qp4 = (const float4*)(g_qraw +
                        ((size_t)s * B_DIM + b) * E_DIM + h * D_DIM);

    float acc[2][8];
#pragma unroll
    for (int r = 0; r < 2; r++)
#pragma unroll
        for (int m = 0; m < 8; m++) acc[r][m] = 0.f;

    for (int d4 = 0; d4 < 32; d4++) {
        float4 qv = qp4[d4];
#pragma unroll
        for (int r = 0; r < 2; r++) {
            const float* h0 = &hw[r][(d4 * 4 + 0) * 8];
            const float* h1 = &hw[r][(d4 * 4 + 1) * 8];
            const float* h2 = &hw[r][(d4 * 4 + 2) * 8];
            const float* h3 = &hw[r][(d4 * 4 + 3) * 8];
#pragma unroll
            for (int m = 0; m < 8; m++) {
                acc[r][m] += qv.x * h0[m];
                acc[r][m] += qv.y * h1[m];
                acc[r][m] += qv.z * h2[m];
                acc[r][m] += qv.w * h3[m];
            }
        }
    }
#pragma unroll
    for (int r = 0; r < 2; r++) {
        float best = acc[r][0]; int bi = 0;
#pragma unroll
        for (int m = 1; m < 8; m++) if (acc[r][m] > best) { best = acc[r][m]; bi = m; }
#pragma unroll
        for (int m = 0; m < 8; m++) if (-acc[r][m] > best) { best = -acc[r][m]; bi = 8 + m; }
        int seg = (b * R_DIM + r) * H_DIM + h;
        g_hash[(size_t)seg * S_DIM + s] = bi;
    }
}

// ---------------- stable counting sort (16 buckets) ----------------
__global__ void sort_kernel()
{
    const int seg = blockIdx.x;
    const int tid = threadIdx.x;
    __shared__ int tc[512][16];
    __shared__ int base[16], tot[16];

    const int* hp = g_hash + (size_t)seg * S_DIM;
#pragma unroll
    for (int m = 0; m < 16; m++) tc[tid][m] = 0;
    int myh[8];
#pragma unroll
    for (int i = 0; i < 8; i++) {
        myh[i] = hp[tid * 8 + i];
        tc[tid][myh[i]]++;
    }
    __syncthreads();
    if (tid < 16) {
        int run = 0;
        for (int t = 0; t < 512; t++) { int v = tc[t][tid]; tc[t][tid] = run; run += v; }
        tot[tid] = run;
    }
    __syncthreads();
    if (tid == 0) {
        int run = 0;
#pragma unroll
        for (int m = 0; m < 16; m++) { base[m] = run; run += tot[m]; }
    }
    __syncthreads();
#pragma unroll
    for (int i = 0; i < 8; i++) {
        int hh = myh[i];
        int pos = base[hh] + tc[tid][hh];
        tc[tid][hh]++;
        g_sidx[(size_t)seg * S_DIM + pos]  = tid * 8 + i;
        g_shash[(size_t)seg * S_DIM + pos] = hh;
    }
}

// ---------------- chunked LSH attention: QK and PV via bf16 mma ------
#define LGS 196
#define RSA 68    // u32 stride for QK 64-row tiles
#define RSP 100   // u32 stride for P rows (96 pairs + pad)
#define RSV 33    // u32 stride for Vt rows (32 pairs + pad)
#define UN_U32 (2*64*RSP + 2*128*RSV)   // >= QK's 4*64*RSA
#define ATTN_SMEM ((64*LGS + UN_U32 + 2*S_DIM) * 4)

__global__ void __launch_bounds__(256) attn_kernel()
{
    extern __shared__ float sm[];
    float* lg = sm;                               // [64][LGS] fp32
    uint32_t* un = (uint32_t*)(sm + 64 * LGS);    // union region
    uint32_t* qh = un;                            // [64][RSA]
    uint32_t* ql = un + 64 * RSA;
    uint32_t* kh = un + 2 * 64 * RSA;
    uint32_t* kl = un + 3 * 64 * RSA;
    uint32_t* ph  = un;                           // [64][RSP]
    uint32_t* pl  = un + 64 * RSP;
    uint32_t* vth = un + 2 * 64 * RSP;            // [128][RSV]
    uint32_t* vtl = vth + 128 * RSV;
    int* sidx_sh  = (int*)(sm + 64 * LGS + UN_U32);
    int* shash_sh = sidx_sh + S_DIM;

    const int bid = blockIdx.x;
    const int n   = bid % NC_DIM;
    const int seg = bid / NC_DIM;
    const int b   = seg / (R_DIM * H_DIM);
    const int h   = seg % H_DIM;
    const int tid = threadIdx.x;
    const int wid = tid >> 5, lane = tid & 31;
    const int g = lane >> 2, t = lane & 3;
    const int warp_m = wid & 1, warp_n = wid >> 1;

    const int* gsidx  = g_sidx  + (size_t)seg * S_DIM;
    const int* gshash = g_shash + (size_t)seg * S_DIM;
    for (int i = tid; i < S_DIM; i += 256) {
        sidx_sh[i]  = gsidx[i];
        shash_sh[i] = gshash[i];
    }
    __syncthreads();

    // ---- stage q hi/lo (pre-scaled, pre-split) ----
#pragma unroll
    for (int i = 0; i < 4; i++) {
        int f = i * 256 + tid; int row = f >> 4; int c16 = f & 15;
        int tok = sidx_sh[n * 64 + row];
        size_t rb = ((size_t)tok * B_DIM + b) * (E_DIM / 2) + h * (D_DIM / 2);
        *(uint4*)&qh[row * RSA + c16 * 4] = *(const uint4*)&g_qsh[rb + c16 * 4];
        *(uint4*)&ql[row * RSA + c16 * 4] = *(const uint4*)&g_qsl[rb + c16 * 4];
    }

    // ---- QK logits via mma: 3 chunks ----
    for (int c = 0; c < 3; c++) {
        int kchunk = (n + c + NC_DIM - 1) & (NC_DIM - 1);
        __syncthreads();
#pragma unroll
        for (int i = 0; i < 4; i++) {
            int f = i * 256 + tid; int row = f >> 4; int c16 = f & 15;
            int tok = sidx_sh[kchunk * 64 + row];
            size_t rb = ((size_t)tok * B_DIM + b) * (E_DIM / 2) + h * (D_DIM / 2);
            *(uint4*)&kh[row * RSA + c16 * 4] = *(const uint4*)&g_kbh[rb + c16 * 4];
            *(uint4*)&kl[row * RSA + c16 * 4] = *(const uint4*)&g_kbl[rb + c16 * 4];
        }
        __syncthreads();

        float acc[2][2][4];
#pragma unroll
        for (int mt = 0; mt < 2; mt++)
#pragma unroll
            for (int nt = 0; nt < 2; nt++)
#pragma unroll
                for (int r = 0; r < 4; r++) acc[mt][nt][r] = 0.f;

#pragma unroll
        for (int ks = 0; ks < 8; ks++) {
            const int j0 = ks * 8;
            uint32_t af[2][4], bh2[2][2];
#pragma unroll
            for (int mt = 0; mt < 2; mt++) {
                int r0 = warp_m * 32 + mt * 16 + g;
                af[mt][0] = qh[r0 * RSA + j0 + t];
                af[mt][1] = qh[(r0 + 8) * RSA + j0 + t];
                af[mt][2] = qh[r0 * RSA + j0 + 4 + t];
                af[mt][3] = qh[(r0 + 8) * RSA + j0 + 4 + t];
            }
#pragma unroll
            for (int nt = 0; nt < 2; nt++) {
                int k0 = warp_n * 16 + nt * 8 + g;
                bh2[nt][0] = kh[k0 * RSA + j0 + t];
                bh2[nt][1] = kh[k0 * RSA + j0 + 4 + t];
            }
#pragma unroll
            for (int mt = 0; mt < 2; mt++)
#pragma unroll
                for (int nt = 0; nt < 2; nt++)
                    mma_bf16(acc[mt][nt], af[mt], bh2[nt]);

            uint32_t bl2[2][2];
#pragma unroll
            for (int nt = 0; nt < 2; nt++) {
                int k0 = warp_n * 16 + nt * 8 + g;
                bl2[nt][0] = kl[k0 * RSA + j0 + t];
                bl2[nt][1] = kl[k0 * RSA + j0 + 4 + t];
            }
#pragma unroll
            for (int mt = 0; mt < 2; mt++)
#pragma unroll
                for (int nt = 0; nt < 2; nt++)
                    mma_bf16(acc[mt][nt], af[mt], bl2[nt]);

#pragma unroll
            for (int mt = 0; mt < 2; mt++) {
                int r0 = warp_m * 32 + mt * 16 + g;
                af[mt][0] = ql[r0 * RSA + j0 + t];
                af[mt][1] = ql[(r0 + 8) * RSA + j0 + t];
                af[mt][2] = ql[r0 * RSA + j0 + 4 + t];
                af[mt][3] = ql[(r0 + 8) * RSA + j0 + 4 + t];
            }
#pragma unroll
            for (int mt = 0; mt < 2; mt++)
#pragma unroll
                for (int nt = 0; nt < 2; nt++)
                    mma_bf16(acc[mt][nt], af[mt], bh2[nt]);
        }

        // ---- masks + writeback (slot-indexed mask windows) ----
#pragma unroll
        for (int mt = 0; mt < 2; mt++) {
            int qq0 = warp_m * 32 + mt * 16 + g;
            int qq1 = qq0 + 8;
            int qh0 = shash_sh[n * 64 + qq0], qt0 = sidx_sh[n * 64 + qq0];
            int qh1 = shash_sh[n * 64 + qq1], qt1 = sidx_sh[n * 64 + qq1];
            int mb0 = ((qq0 + c + NC_DIM - 1) & (NC_DIM - 1)) * 64;
            int mb1 = ((qq1 + c + NC_DIM - 1) & (NC_DIM - 1)) * 64;
#pragma unroll
            for (int nt = 0; nt < 2; nt++) {
                int jj = warp_n * 16 + nt * 8 + 2 * t;
                float v00 = acc[mt][nt][0], v01 = acc[mt][nt][1];
                float v10 = acc[mt][nt][2], v11 = acc[mt][nt][3];
                if (qh0 != shash_sh[mb0 + jj])     v00 = NEG_F;
                if (qt0 == sidx_sh[mb0 + jj])      v00 = NEG_SELF_F;
                if (qh0 != shash_sh[mb0 + jj + 1]) v01 = NEG_F;
                if (qt0 == sidx_sh[mb0 + jj + 1])  v01 = NEG_SELF_F;
                if (qh1 != shash_sh[mb1 + jj])     v10 = NEG_F;
                if (qt1 == sidx_sh[mb1 + jj])      v10 = NEG_SELF_F;
                if (qh1 != shash_sh[mb1 + jj + 1]) v11 = NEG_F;
                if (qt1 == sidx_sh[mb1 + jj + 1])  v11 = NEG_SELF_F;
                *(float2*)&lg[qq0 * LGS + c * 64 + jj] = make_float2(v00, v01);
                *(float2*)&lg[qq1 * LGS + c * 64 + jj] = make_float2(v10, v11);
            }
        }
    }
    __syncthreads();

    // ---- softmax + lse: 4 threads per query row ----
    {
        const int row = tid >> 2, p = tid & 3;
        float* lrow = &lg[row * LGS];
        float m = -3.402823466e38f;
        for (int j = p; j < 192; j += 4) m = fmaxf(m, lrow[j]);
        m = fmaxf(m, __shfl_xor_sync(0xffffffffu, m, 1));
        m = fmaxf(m, __shfl_xor_sync(0xffffffffu, m, 2));
        float ssum = 0.f;
        for (int j = p; j < 192; j += 4) {
            float e = __expf(lrow[j] - m);
            lrow[j] = e;
            ssum += e;
        }
        ssum += __shfl_xor_sync(0xffffffffu, ssum, 1);
        ssum += __shfl_xor_sync(0xffffffffu, ssum, 2);
        float inv = 1.0f / ssum;
        for (int j = p; j < 192; j += 4) lrow[j] *= inv;
        if (p == 0)
            g_olse[(size_t)seg * S_DIM + sidx_sh[n * 64 + row]] = m + __logf(ssum);
    }
    __syncthreads();

    // ---- P -> bf16 hi/lo (pairs along w) ----
    {
        const int row = tid >> 2, p = tid & 3;
        const float* lrow = &lg[row * LGS];
        for (int jj = p; jj < 96; jj += 4) {
            uint32_t hh, ll;
            split2(lrow[2 * jj], lrow[2 * jj + 1], hh, ll);
            ph[row * RSP + jj] = hh;
            pl[row * RSP + jj] = ll;
        }
    }

    // ---- PV via bf16 mma: 3 chunks; V pre-split, transpose via PRMT ----
    float oacc[2][4][4];
#pragma unroll
    for (int mt = 0; mt < 2; mt++)
#pragma unroll
        for (int nt = 0; nt < 4; nt++)
#pragma unroll
            for (int r = 0; r < 4; r++) oacc[mt][nt][r] = 0.f;

    for (int c = 0; c < 3; c++) {
        int kchunk = (n + c + NC_DIM - 1) & (NC_DIM - 1);
        __syncthreads();
        // stage Vt chunk: per task one (w-pair, d-pair) cell; PRMT repack
#pragma unroll
        for (int i = 0; i < 8; i++) {
            int idx = i * 256 + tid;         // 0..2047
            int wp = idx >> 6;               // 0..31 (token pair)
            int dp = idx & 63;               // 0..63 (d pair)
            int tok0 = sidx_sh[kchunk * 64 + 2 * wp];
            int tok1 = sidx_sh[kchunk * 64 + 2 * wp + 1];
            size_t rb0 = ((size_t)tok0 * B_DIM + b) * (E_DIM / 2) + h * (D_DIM / 2) + dp;
            size_t rb1 = ((size_t)tok1 * B_DIM + b) * (E_DIM / 2) + h * (D_DIM / 2) + dp;
            uint32_t h0 = g_vbh[rb0], h1 = g_vbh[rb1];
            uint32_t l0 = g_vbl[rb0], l1 = g_vbl[rb1];
            vth[(2 * dp) * RSV + wp]     = prmt(h0, h1, 0x5410u);
            vth[(2 * dp + 1) * RSV + wp] = prmt(h0, h1, 0x7632u);
            vtl[(2 * dp) * RSV + wp]     = prmt(l0, l1, 0x5410u);
            vtl[(2 * dp + 1) * RSV + wp] = prmt(l0, l1, 0x7632u);
        }
        __syncthreads();

#pragma unroll
        for (int ks = 0; ks < 4; ks++) {
            const int j0p = c * 32 + ks * 8;
            const int j0v = ks * 8;
            uint32_t af[2][4], bh2[4][2];
#pragma unroll
            for (int mt = 0; mt < 2; mt++) {
                int r0 = warp_m * 32 + mt * 16 + g;
                af[mt][0] = ph[r0 * RSP + j0p + t];
                af[mt][1] = ph[(r0 + 8) * RSP + j0p + t];
                af[mt][2] = ph[r0 * RSP + j0p + 4 + t];
                af[mt][3] = ph[(r0 + 8) * RSP + j0p + 4 + t];
            }
#pragma unroll
            for (int nt = 0; nt < 4; nt++) {
                int n0 = warp_n * 32 + nt * 8 + g;
                bh2[nt][0] = vth[n0 * RSV + j0v + t];
                bh2[nt][1] = vth[n0 * RSV + j0v + 4 + t];
            }
#pragma unroll
            for (int mt = 0; mt < 2; mt++)
#pragma unroll
                for (int nt = 0; nt < 4; nt++)
                    mma_bf16(oacc[mt][nt], af[mt], bh2[nt]);

            uint32_t bl2[4][2];
#pragma unroll
            for (int nt = 0; nt < 4; nt++) {
                int n0 = warp_n * 32 + nt * 8 + g;
                bl2[nt][0] = vtl[n0 * RSV + j0v + t];
                bl2[nt][1] = vtl[n0 * RSV + j0v + 4 + t];
            }
#pragma unroll
            for (int mt = 0; mt < 2; mt++)
#pragma unroll
                for (int nt = 0; nt < 4; nt++)
                    mma_bf16(oacc[mt][nt], af[mt], bl2[nt]);

#pragma unroll
            for (int mt = 0; mt < 2; mt++) {
                int r0 = warp_m * 32 + mt * 16 + g;
                af[mt][0] = pl[r0 * RSP + j0p + t];
                af[mt][1] = pl[(r0 + 8) * RSP + j0p + t];
                af[mt][2] = pl[r0 * RSP + j0p + 4 + t];
                af[mt][3] = pl[(r0 + 8) * RSP + j0p + 4 + t];
            }
#pragma unroll
            for (int mt = 0; mt < 2; mt++)
#pragma unroll
                for (int nt = 0; nt < 4; nt++)
                    mma_bf16(oacc[mt][nt], af[mt], bh2[nt]);
        }
    }

    // ---- epilogue: scatter O to original token order ----
#pragma unroll
    for (int mt = 0; mt < 2; mt++) {
        int q0 = warp_m * 32 + mt * 16 + g;
        int tok0 = sidx_sh[n * 64 + q0];
        int tok1 = sidx_sh[n * 64 + q0 + 8];
        size_t b0 = ((size_t)seg * S_DIM + tok0) * D_DIM;
        size_t b1 = ((size_t)seg * S_DIM + tok1) * D_DIM;
#pragma unroll
        for (int nt = 0; nt < 4; nt++) {
            int d0 = warp_n * 32 + nt * 8 + 2 * t;
            *(float2*)&g_oout[b0 + d0] = make_float2(oacc[mt][nt][0], oacc[mt][nt][1]);
            *(float2*)&g_oout[b1 + d0] = make_float2(oacc[mt][nt][2], oacc[mt][nt][3]);
        }
    }
}

// ------- combine rounds by softmax over lse; writes bf16 hi/lo directly ----
__global__ void combine_kernel()
{
    const int g = blockIdx.x * 256 + threadIdx.x;
    const int flat = g * 4;
    const int e = flat & (E_DIM - 1);
    const int sb = flat >> 10;
    const int b = sb & 1;
    const int s = sb >> 1;
    const int h = e >> 7;
    const int d = e & 127;

    const int seg0 = (b * R_DIM + 0) * H_DIM + h;
    const int seg1 = (b * R_DIM + 1) * H_DIM + h;

    float l0 = g_olse[(size_t)seg0 * S_DIM + s];
    float l1 = g_olse[(size_t)seg1 * S_DIM + s];
    float m = fmaxf(l0, l1);
    float e0 = __expf(l0 - m), e1 = __expf(l1 - m);
    float inv = 1.0f / (e0 + e1);
    float w0 = e0 * inv, w1 = e1 * inv;

    float4 o0 = *(const float4*)&g_oout[((size_t)seg0 * S_DIM + s) * D_DIM + d];
    float4 o1 = *(const float4*)&g_oout[((size_t)seg1 * S_DIM + s) * D_DIM + d];
    float4 r;
    r.x = w0 * o0.x + w1 * o1.x;
    r.y = w0 * o0.y + w1 * o1.y;
    r.z = w0 * o0.z + w1 * o1.z;
    r.w = w0 * o0.w + w1 * o1.w;
    uint2 hh, ll;
    split2(r.x, r.y, hh.x, ll.x);
    split2(r.z, r.w, hh.y, ll.y);
    ((uint2*)g_och)[g] = hh;
    ((uint2*)g_ocl)[g] = ll;
}

// ---------------- launcher ----------------
extern "C" void kernel_launch(void* const* d_in, const int* in_sizes, int n_in,
                              void* d_out, int out_size)
{
    const float* x      = (const float*)d_in[0];
    const float* wq     = (const float*)d_in[1];
    const float* bq     = (const float*)d_in[2];
    const float* wv     = (const float*)d_in[3];
    const float* bv     = (const float*)d_in[4];
    const float* wo     = (const float*)d_in[5];
    const float* bo     = (const float*)d_in[6];
    const float* hash_w = (const float*)d_in[7];
    float* out = (float*)d_out;

    float* p_qraw;
    uint32_t *p_xh, *p_xl, *p_wvh, *p_wvl, *p_woh, *p_wol;
    uint32_t *p_och, *p_ocl, *p_vbh, *p_vbl;
    cudaGetSymbolAddress((void**)&p_qraw, g_qraw);
    cudaGetSymbolAddress((void**)&p_xh,  g_xh);  cudaGetSymbolAddress((void**)&p_xl,  g_xl);
    cudaGetSymbolAddress((void**)&p_wvh, g_wvh); cudaGetSymbolAddress((void**)&p_wvl, g_wvl);
    cudaGetSymbolAddress((void**)&p_woh, g_woh); cudaGetSymbolAddress((void**)&p_wol, g_wol);
    cudaGetSymbolAddress((void**)&p_och, g_och); cudaGetSymbolAddress((void**)&p_ocl, g_ocl);
    cudaGetSymbolAddress((void**)&p_vbh, g_vbh); cudaGetSymbolAddress((void**)&p_vbl, g_vbl);

    cudaFuncSetAttribute(attn_kernel, cudaFuncAttributeMaxDynamicSharedMemorySize,
                         ATTN_SMEM);
    cudaFuncSetAttribute(gemm_bf16_kernel<true>,
                         cudaFuncAttributeMaxDynamicSharedMemorySize, BGEMM_SMEM);
    cudaFuncSetAttribute(gemm_bf16_kernel<false>,
                         cudaFuncAttributeMaxDynamicSharedMemorySize, BGEMM_SMEM);

    dim3 gemm_grid(E_DIM / 128, MROWS / 128);
    const int nsplit = N4X + 2 * N4W;

    // pre-split x, wv, wo for bf16 GEMMs (one merged launch)
    split_all_kernel<<<(nsplit + 255) / 256, 256>>>((const float4*)x,
                                                    (const float4*)wv,
                                                    (const float4*)wo);
    // q: SIMT fp32 (flip-free); v: bf16 mma split with SPLIT output
    gemm_bias_kernel<<<gemm_grid, 256>>>(x, wq, bq, p_qraw);
    gemm_bf16_kernel<true><<<gemm_grid, 256, BGEMM_SMEM>>>(
        p_xh, p_xl, p_wvh, p_wvl, bv, nullptr, p_vbh, p_vbl);

    norm_split_kernel<<<MROWS, 256>>>();
    hash_kernel<<<dim3(S_DIM / 256, B_DIM * H_DIM), 256>>>(hash_w);
    sort_kernel<<<NSEG, 512>>>();
    attn_kernel<<<NSEG * NC_DIM, 256, ATTN_SMEM>>>();
    combine_kernel<<<MROWS * E_DIM / 4 / 256, 256>>>();
    gemm_bf16_kernel<false><<<gemm_grid, 256, BGEMM_SMEM>>>(
        p_och, p_ocl, p_woh, p_wol, bo, out, nullptr, nullptr);
}

// round 15
// speedup vs baseline: 1.1191x; 1.1191x over previous
#include <cuda_runtime.h>
#include <cuda_bf16.h>
#include <math.h>
#include <stdint.h>

// ---------------- problem dims ----------------
#define S_DIM 4096
#define B_DIM 2
#define E_DIM 1024
#define H_DIM 8
#define R_DIM 2
#define C_DIM 64
#define D_DIM 128
#define NC_DIM 64                    // S / C
#define NSEG (B_DIM*R_DIM*H_DIM)     // 32
#define MROWS (S_DIM*B_DIM)          // 8192
#define SCALE_F 0.08838834764831845f // D^-0.5
#define NEG_F (-1e9f)
#define NEG_SELF_F (-1e5f)

// ---------------- scratch (device globals; no allocation) ----------------
__device__ float g_qraw[MROWS*E_DIM];     // x@wq^T + bq (fp32, feeds hash)
__device__ float g_v[MROWS*E_DIM];        // x@wv^T + bv
__device__ float g_oout[NSEG*S_DIM*D_DIM];
__device__ float g_olse[NSEG*S_DIM];
__device__ int   g_hash[NSEG*S_DIM];
__device__ int   g_sidx[NSEG*S_DIM];
__device__ int   g_shash[NSEG*S_DIM];
// pre-split bf16 hi/lo (u32 = bf16x2 pairs along last dim)
__device__ uint32_t g_xh[MROWS*E_DIM/2], g_xl[MROWS*E_DIM/2];
__device__ uint32_t g_wvh[E_DIM*E_DIM/2], g_wvl[E_DIM*E_DIM/2];
__device__ uint32_t g_woh[E_DIM*E_DIM/2], g_wol[E_DIM*E_DIM/2];
__device__ uint32_t g_och[MROWS*E_DIM/2], g_ocl[MROWS*E_DIM/2]; // combined o
__device__ uint32_t g_qsh[MROWS*E_DIM/2], g_qsl[MROWS*E_DIM/2]; // scaled q
__device__ uint32_t g_kbh[MROWS*E_DIM/2], g_kbl[MROWS*E_DIM/2]; // normalized k

// ---------------- bf16 split helpers ----------------
__device__ __forceinline__ void split2(float a, float b, uint32_t& h, uint32_t& l) {
    __nv_bfloat162 hh = __floats2bfloat162_rn(a, b);
    h = *reinterpret_cast<uint32_t*>(&hh);
    __nv_bfloat162 ll = __floats2bfloat162_rn(a - __bfloat162float(hh.x),
                                              b - __bfloat162float(hh.y));
    l = *reinterpret_cast<uint32_t*>(&ll);
}

__device__ __forceinline__ void mma_bf16(float* d, const uint32_t* a,
                                         const uint32_t* b) {
    asm volatile(
        "mma.sync.aligned.m16n8k16.row.col.f32.bf16.bf16.f32 "
        "{%0,%1,%2,%3}, {%4,%5,%6,%7}, {%8,%9}, {%0,%1,%2,%3};\n"
        : "+f"(d[0]), "+f"(d[1]), "+f"(d[2]), "+f"(d[3])
        : "r"(a[0]), "r"(a[1]), "r"(a[2]), "r"(a[3]), "r"(b[0]), "r"(b[1]));
}

// ---------------- merged split conversion kernel (memory-bound) --------
#define N4X (MROWS*E_DIM/4)
#define N4W (E_DIM*E_DIM/4)
__global__ void split_all_kernel(const float4* __restrict__ x,
                                 const float4* __restrict__ wv,
                                 const float4* __restrict__ wo)
{
    int i = blockIdx.x * 256 + threadIdx.x;
    const float4* src; uint2 *dh, *dl; int j;
    if (i < N4X) {
        src = x; dh = (uint2*)g_xh; dl = (uint2*)g_xl; j = i;
    } else if (i < N4X + N4W) {
        src = wv; dh = (uint2*)g_wvh; dl = (uint2*)g_wvl; j = i - N4X;
    } else {
        src = wo; dh = (uint2*)g_woh; dl = (uint2*)g_wol; j = i - N4X - N4W;
    }
    float4 v = src[j];
    uint2 h, l;
    split2(v.x, v.y, h.x, l.x);
    split2(v.z, v.w, h.y, l.y);
    dh[j] = h; dl[j] = l;
}

// =====================================================================
// SIMT fp32 GEMM (q projection ONLY — flip-free path).
// =====================================================================
__global__ void __launch_bounds__(256)
gemm_bias_kernel(const float* __restrict__ A,
                 const float* __restrict__ W,
                 const float* __restrict__ bias,
                 float* __restrict__ C,
                 int M, int N, int K)
{
    __shared__ float As[2][16][132];
    __shared__ float Ws[2][16][132];

    const int tid = threadIdx.x;
    const int bm = blockIdx.y * 128;
    const int bn = blockIdx.x * 128;
    const int tm = tid >> 4;
    const int tn = tid & 15;

    float acc[8][8];
#pragma unroll
    for (int i = 0; i < 8; i++)
#pragma unroll
        for (int j = 0; j < 8; j++) acc[i][j] = 0.f;

    float4 ha[2], hw[2];

#define GLD(k0)                                                            \
    {                                                                      \
        _Pragma("unroll")                                                  \
        for (int it = 0; it < 2; it++) {                                   \
            int l = it * 256 + tid; int m = l >> 2; int kq = (l & 3) * 4;  \
            ha[it] = *(const float4*)&A[(size_t)(bm + m) * K + (k0) + kq]; \
            hw[it] = *(const float4*)&W[(size_t)(bn + m) * K + (k0) + kq]; \
        }                                                                  \
    }
#define GST(nb)                                                            \
    {                                                                      \
        _Pragma("unroll")                                                  \
        for (int it = 0; it < 2; it++) {                                   \
            int l = it * 256 + tid; int m = l >> 2; int kq = (l & 3) * 4;  \
            As[nb][kq + 0][m] = ha[it].x; As[nb][kq + 1][m] = ha[it].y;    \
            As[nb][kq + 2][m] = ha[it].z; As[nb][kq + 3][m] = ha[it].w;    \
            Ws[nb][kq + 0][m] = hw[it].x; Ws[nb][kq + 1][m] = hw[it].y;    \
            Ws[nb][kq + 2][m] = hw[it].z; Ws[nb][kq + 3][m] = hw[it].w;    \
        }                                                                  \
    }

    GLD(0); GST(0); __syncthreads();

    const int nIter = K >> 4;
    for (int ii = 0; ii < nIter; ii++) {
        if (ii + 1 < nIter) GLD((ii + 1) << 4);
        const int cb = ii & 1;
#pragma unroll
        for (int k = 0; k < 16; k++) {
            float4 a0 = *(const float4*)&As[cb][k][tm * 8];
            float4 a1 = *(const float4*)&As[cb][k][tm * 8 + 4];
            float4 b0 = *(const float4*)&Ws[cb][k][tn * 8];
            float4 b1 = *(const float4*)&Ws[cb][k][tn * 8 + 4];
            float av[8] = {a0.x, a0.y, a0.z, a0.w, a1.x, a1.y, a1.z, a1.w};
            float bv[8] = {b0.x, b0.y, b0.z, b0.w, b1.x, b1.y, b1.z, b1.w};
#pragma unroll
            for (int i = 0; i < 8; i++)
#pragma unroll
                for (int j = 0; j < 8; j++) acc[i][j] += av[i] * bv[j];
        }
        if (ii + 1 < nIter) GST((ii + 1) & 1);
        __syncthreads();
    }
#undef GLD
#undef GST

    float4 bb0 = *(const float4*)&bias[bn + tn * 8];
    float4 bb1 = *(const float4*)&bias[bn + tn * 8 + 4];
#pragma unroll
    for (int i = 0; i < 8; i++) {
        float4 o0, o1;
        o0.x = acc[i][0] + bb0.x; o0.y = acc[i][1] + bb0.y;
        o0.z = acc[i][2] + bb0.z; o0.w = acc[i][3] + bb0.w;
        o1.x = acc[i][4] + bb1.x; o1.y = acc[i][5] + bb1.y;
        o1.z = acc[i][6] + bb1.z; o1.w = acc[i][7] + bb1.w;
        size_t rowoff = (size_t)(bm + tm * 8 + i) * N + bn + tn * 8;
        *(float4*)&C[rowoff]     = o0;
        *(float4*)&C[rowoff + 4] = o1;
    }
}

// =====================================================================
// bf16 mma split GEMM with PRE-CONVERTED hi/lo inputs (v/o projections).
// =====================================================================
#define RS 20
#define BGEMM_SMEM (2 * 4 * 128 * RS * 4)

__global__ void __launch_bounds__(256)
gemm_bf16_kernel(const uint32_t* __restrict__ Ah, const uint32_t* __restrict__ Al,
                 const uint32_t* __restrict__ Wh, const uint32_t* __restrict__ Wl,
                 const float* __restrict__ bias, float* __restrict__ C,
                 int M, int N, int K)
{
    extern __shared__ uint32_t bsm[];
    uint32_t* base[2];
    base[0] = bsm;
    base[1] = bsm + 4 * 128 * RS;

    const int tid = threadIdx.x;
    const int wid = tid >> 5, lane = tid & 31;
    const int g = lane >> 2, t = lane & 3;
    const int warp_m = wid & 1;
    const int warp_n = wid >> 1;
    const int bm = blockIdx.y * 128, bn = blockIdx.x * 128;
    const int K2 = K >> 1;

    float acc[4][4][4];
#pragma unroll
    for (int mi = 0; mi < 4; mi++)
#pragma unroll
        for (int ni = 0; ni < 4; ni++)
#pragma unroll
            for (int r = 0; r < 4; r++) acc[mi][ni][r] = 0.f;

    uint4 rah[2], ral[2], rwh[2], rwl[2];

#define BGLD(k02)                                                            \
    {                                                                        \
        _Pragma("unroll")                                                    \
        for (int it = 0; it < 2; it++) {                                     \
            int task = it * 256 + tid; int row = task >> 2; int q4 = task & 3;\
            size_t oa = (size_t)(bm + row) * K2 + (k02) + q4 * 4;            \
            size_t ow = (size_t)(bn + row) * K2 + (k02) + q4 * 4;            \
            rah[it] = *(const uint4*)&Ah[oa]; ral[it] = *(const uint4*)&Al[oa];\
            rwh[it] = *(const uint4*)&Wh[ow]; rwl[it] = *(const uint4*)&Wl[ow];\
        }                                                                    \
    }
#define BGST(nb)                                                             \
    {                                                                        \
        uint32_t* sAh = base[nb];                                            \
        uint32_t* sAl = sAh + 128 * RS;                                      \
        uint32_t* sBh = sAl + 128 * RS;                                      \
        uint32_t* sBl = sBh + 128 * RS;                                      \
        _Pragma("unroll")                                                    \
        for (int it = 0; it < 2; it++) {                                     \
            int task = it * 256 + tid; int row = task >> 2; int q4 = task & 3;\
            int off = row * RS + q4 * 4;                                     \
            *(uint4*)&sAh[off] = rah[it]; *(uint4*)&sAl[off] = ral[it];      \
            *(uint4*)&sBh[off] = rwh[it]; *(uint4*)&sBl[off] = rwl[it];      \
        }                                                                    \
    }

    BGLD(0); BGST(0); __syncthreads();

    const int nIter = K >> 5;
    for (int ii = 0; ii < nIter; ii++) {
        if (ii + 1 < nIter) BGLD((ii + 1) * 16);
        const uint32_t* Ahs = base[ii & 1];
        const uint32_t* Als = Ahs + 128 * RS;
        const uint32_t* Bhs = Als + 128 * RS;
        const uint32_t* Bls = Bhs + 128 * RS;

#pragma unroll
        for (int s = 0; s < 2; s++) {
            const int j0 = s * 8;
            uint32_t af[4][4], bh[4][2];
#pragma unroll
            for (int mi = 0; mi < 4; mi++) {
                int r0 = warp_m * 64 + mi * 16 + g;
                af[mi][0] = Ahs[r0 * RS + j0 + t];
                af[mi][1] = Ahs[(r0 + 8) * RS + j0 + t];
                af[mi][2] = Ahs[r0 * RS + j0 + 4 + t];
                af[mi][3] = Ahs[(r0 + 8) * RS + j0 + 4 + t];
            }
#pragma unroll
            for (int ni = 0; ni < 4; ni++) {
                int n0 = warp_n * 32 + ni * 8 + g;
                bh[ni][0] = Bhs[n0 * RS + j0 + t];
                bh[ni][1] = Bhs[n0 * RS + j0 + 4 + t];
            }
#pragma unroll
            for (int mi = 0; mi < 4; mi++)
#pragma unroll
                for (int ni = 0; ni < 4; ni++)
                    mma_bf16(acc[mi][ni], af[mi], bh[ni]);

            uint32_t bl[4][2];
#pragma unroll
            for (int ni = 0; ni < 4; ni++) {
                int n0 = warp_n * 32 + ni * 8 + g;
                bl[ni][0] = Bls[n0 * RS + j0 + t];
                bl[ni][1] = Bls[n0 * RS + j0 + 4 + t];
            }
#pragma unroll
            for (int mi = 0; mi < 4; mi++)
#pragma unroll
                for (int ni = 0; ni < 4; ni++)
                    mma_bf16(acc[mi][ni], af[mi], bl[ni]);

#pragma unroll
            for (int mi = 0; mi < 4; mi++) {
                int r0 = warp_m * 64 + mi * 16 + g;
                af[mi][0] = Als[r0 * RS + j0 + t];
                af[mi][1] = Als[(r0 + 8) * RS + j0 + t];
                af[mi][2] = Als[r0 * RS + j0 + 4 + t];
                af[mi][3] = Als[(r0 + 8) * RS + j0 + 4 + t];
            }
#pragma unroll
            for (int mi = 0; mi < 4; mi++)
#pragma unroll
                for (int ni = 0; ni < 4; ni++)
                    mma_bf16(acc[mi][ni], af[mi], bh[ni]);
        }
        if (ii + 1 < nIter) BGST((ii + 1) & 1);
        __syncthreads();
    }
#undef BGLD
#undef BGST

#pragma unroll
    for (int mi = 0; mi < 4; mi++) {
        int row0 = bm + warp_m * 64 + mi * 16 + g;
#pragma unroll
        for (int ni = 0; ni < 4; ni++) {
            int col = bn + warp_n * 32 + ni * 8 + 2 * t;
            float b0 = bias[col], b1 = bias[col + 1];
            *(float2*)&C[(size_t)row0 * N + col] =
                make_float2(acc[mi][ni][0] + b0, acc[mi][ni][1] + b1);
            *(float2*)&C[(size_t)(row0 + 8) * N + col] =
                make_float2(acc[mi][ni][2] + b0, acc[mi][ni][3] + b1);
        }
    }
}

// ---------------- fused norm + split: k = q/||q|| and qs = q*SCALE ----
__global__ void norm_split_kernel()
{
    const int row = blockIdx.x;
    const int tid = threadIdx.x;      // 256
    const float4* q4 = (const float4*)(g_qraw + (size_t)row * E_DIM);
    float4 v = q4[tid];
    float ss = v.x * v.x + v.y * v.y + v.z * v.z + v.w * v.w;
#pragma unroll
    for (int o = 16; o > 0; o >>= 1) ss += __shfl_xor_sync(0xffffffffu, ss, o);
    __shared__ float red[8];
    __shared__ float s_inv;
    if ((tid & 31) == 0) red[tid >> 5] = ss;
    __syncthreads();
    if (tid == 0) {
        float tt = 0.f;
#pragma unroll
        for (int i = 0; i < 8; i++) tt += red[i];
        s_inv = 1.0f / sqrtf(tt);
    }
    __syncthreads();
    const float inv = s_inv;

    const int idx = row * 256 + tid;  // uint2 index
    uint2 h, l;
    split2(v.x * inv, v.y * inv, h.x, l.x);
    split2(v.z * inv, v.w * inv, h.y, l.y);
    ((uint2*)g_kbh)[idx] = h; ((uint2*)g_kbl)[idx] = l;
    split2(v.x * SCALE_F, v.y * SCALE_F, h.x, l.x);
    split2(v.z * SCALE_F, v.w * SCALE_F, h.y, l.y);
    ((uint2*)g_qsh)[idx] = h; ((uint2*)g_qsl)[idx] = l;
}

// ---------------- LSH hashing: both rounds fused (verified win) -------
__global__ void hash_kernel(const float* __restrict__ hash_w)
{
    const int bh = blockIdx.y;               // b*H + h
    const int b = bh / H_DIM;
    const int h = bh % H_DIM;

    __shared__ float hw[2][D_DIM * 8];
    for (int r = 0; r < 2; r++) {
        const float* hwp = hash_w + (size_t)(r * H_DIM + h) * D_DIM * 8;
        for (int i = threadIdx.x; i < D_DIM * 8; i += 256) hw[r][i] = hwp[i];
    }
    __syncthreads();

    const int s = blockIdx.x * 256 + threadIdx.x;
    const float4* qp4 = (const float4*)(g_qraw +
                        ((size_t)s * B_DIM + b) * E_DIM + h * D_DIM);

    float acc[2][8];
#pragma unroll
    for (int r = 0; r < 2; r++)
#pragma unroll
        for (int m = 0; m < 8; m++) acc[r][m] = 0.f;

    for (int d4 = 0; d4 < 32; d4++) {
        float4 qv = qp4[d4];
#pragma unroll
        for (int r = 0; r < 2; r++) {
            const float* h0 = &hw[r][(d4 * 4 + 0) * 8];
            const float* h1 = &hw[r][(d4 * 4 + 1) * 8];
            const float* h2 = &hw[r][(d4 * 4 + 2) * 8];
            const float* h3 = &hw[r][(d4 * 4 + 3) * 8];
#pragma unroll
            for (int m = 0; m < 8; m++) {
                acc[r][m] += qv.x * h0[m];
                acc[r][m] += qv.y * h1[m];
                acc[r][m] += qv.z * h2[m];
                acc[r][m] += qv.w * h3[m];
            }
        }
    }
#pragma unroll
    for (int r = 0; r < 2; r++) {
        float best = acc[r][0]; int bi = 0;
#pragma unroll
        for (int m = 1; m < 8; m++) if (acc[r][m] > best) { best = acc[r][m]; bi = m; }
#pragma unroll
        for (int m = 0; m < 8; m++) if (-acc[r][m] > best) { best = -acc[r][m]; bi = 8 + m; }
        int seg = (b * R_DIM + r) * H_DIM + h;
        g_hash[(size_t)seg * S_DIM + s] = bi;
    }
}

// ---------------- stable counting sort (16 buckets) ----------------
__global__ void sort_kernel()
{
    const int seg = blockIdx.x;
    const int tid = threadIdx.x;
    __shared__ int tc[512][16];
    __shared__ int base[16], tot[16];

    const int* hp = g_hash + (size_t)seg * S_DIM;
#pragma unroll
    for (int m = 0; m < 16; m++) tc[tid][m] = 0;
    int myh[8];
#pragma unroll
    for (int i = 0; i < 8; i++) {
        myh[i] = hp[tid * 8 + i];
        tc[tid][myh[i]]++;
    }
    __syncthreads();
    if (tid < 16) {
        int run = 0;
        for (int t = 0; t < 512; t++) { int v = tc[t][tid]; tc[t][tid] = run; run += v; }
        tot[tid] = run;
    }
    __syncthreads();
    if (tid == 0) {
        int run = 0;
#pragma unroll
        for (int m = 0; m < 16; m++) { base[m] = run; run += tot[m]; }
    }
    __syncthreads();
#pragma unroll
    for (int i = 0; i < 8; i++) {
        int hh = myh[i];
        int pos = base[hh] + tc[tid][hh];
        tc[tid][hh]++;
        g_sidx[(size_t)seg * S_DIM + pos]  = tid * 8 + i;
        g_shash[(size_t)seg * S_DIM + pos] = hh;
    }
}

// ---------------- chunked LSH attention: QK and PV via bf16 mma ------
#define LGS 196
#define RSA 68    // u32 stride for QK 64-row tiles
#define RSP 100   // u32 stride for P rows (96 pairs + pad)
#define RSV 33    // u32 stride for Vt rows (32 pairs + pad)
#define UN_U32 (2*64*RSP + 2*128*RSV)   // >= QK's 4*64*RSA
#define ATTN_SMEM ((64*LGS + UN_U32 + 2*S_DIM) * 4)

__global__ void __launch_bounds__(256) attn_kernel()
{
    extern __shared__ float sm[];
    float* lg = sm;                               // [64][LGS] fp32
    uint32_t* un = (uint32_t*)(sm + 64 * LGS);    // union region
    uint32_t* qh = un;                            // [64][RSA]
    uint32_t* ql = un + 64 * RSA;
    uint32_t* kh = un + 2 * 64 * RSA;
    uint32_t* kl = un + 3 * 64 * RSA;
    uint32_t* ph  = un;                           // [64][RSP]
    uint32_t* pl  = un + 64 * RSP;
    uint32_t* vth = un + 2 * 64 * RSP;            // [128][RSV]
    uint32_t* vtl = vth + 128 * RSV;
    int* sidx_sh  = (int*)(sm + 64 * LGS + UN_U32);
    int* shash_sh = sidx_sh + S_DIM;

    const int bid = blockIdx.x;
    const int n   = bid % NC_DIM;
    const int seg = bid / NC_DIM;
    const int b   = seg / (R_DIM * H_DIM);
    const int h   = seg % H_DIM;
    const int tid = threadIdx.x;
    const int wid = tid >> 5, lane = tid & 31;
    const int g = lane >> 2, t = lane & 3;
    const int warp_m = wid & 1, warp_n = wid >> 1;

    const int* gsidx  = g_sidx  + (size_t)seg * S_DIM;
    const int* gshash = g_shash + (size_t)seg * S_DIM;
    for (int i = tid; i < S_DIM; i += 256) {
        sidx_sh[i]  = gsidx[i];
        shash_sh[i] = gshash[i];
    }
    __syncthreads();

    // ---- stage q hi/lo (pre-scaled, pre-split) ----
#pragma unroll
    for (int i = 0; i < 4; i++) {
        int f = i * 256 + tid; int row = f >> 4; int c16 = f & 15;
        int tok = sidx_sh[n * 64 + row];
        size_t rb = ((size_t)tok * B_DIM + b) * (E_DIM / 2) + h * (D_DIM / 2);
        *(uint4*)&qh[row * RSA + c16 * 4] = *(const uint4*)&g_qsh[rb + c16 * 4];
        *(uint4*)&ql[row * RSA + c16 * 4] = *(const uint4*)&g_qsl[rb + c16 * 4];
    }

    // ---- QK logits via mma: 3 chunks ----
    for (int c = 0; c < 3; c++) {
        int kchunk = (n + c + NC_DIM - 1) & (NC_DIM - 1);
        __syncthreads();
#pragma unroll
        for (int i = 0; i < 4; i++) {
            int f = i * 256 + tid; int row = f >> 4; int c16 = f & 15;
            int tok = sidx_sh[kchunk * 64 + row];
            size_t rb = ((size_t)tok * B_DIM + b) * (E_DIM / 2) + h * (D_DIM / 2);
            *(uint4*)&kh[row * RSA + c16 * 4] = *(const uint4*)&g_kbh[rb + c16 * 4];
            *(uint4*)&kl[row * RSA + c16 * 4] = *(const uint4*)&g_kbl[rb + c16 * 4];
        }
        __syncthreads();

        float acc[2][2][4];
#pragma unroll
        for (int mt = 0; mt < 2; mt++)
#pragma unroll
            for (int nt = 0; nt < 2; nt++)
#pragma unroll
                for (int r = 0; r < 4; r++) acc[mt][nt][r] = 0.f;

#pragma unroll
        for (int ks = 0; ks < 8; ks++) {
            const int j0 = ks * 8;
            uint32_t af[2][4], bh2[2][2];
#pragma unroll
            for (int mt = 0; mt < 2; mt++) {
                int r0 = warp_m * 32 + mt * 16 + g;
                af[mt][0] = qh[r0 * RSA + j0 + t];
                af[mt][1] = qh[(r0 + 8) * RSA + j0 + t];
                af[mt][2] = qh[r0 * RSA + j0 + 4 + t];
                af[mt][3] = qh[(r0 + 8) * RSA + j0 + 4 + t];
            }
#pragma unroll
            for (int nt = 0; nt < 2; nt++) {
                int k0 = warp_n * 16 + nt * 8 + g;
                bh2[nt][0] = kh[k0 * RSA + j0 + t];
                bh2[nt][1] = kh[k0 * RSA + j0 + 4 + t];
            }
#pragma unroll
            for (int mt = 0; mt < 2; mt++)
#pragma unroll
                for (int nt = 0; nt < 2; nt++)
                    mma_bf16(acc[mt][nt], af[mt], bh2[nt]);

            uint32_t bl2[2][2];
#pragma unroll
            for (int nt = 0; nt < 2; nt++) {
                int k0 = warp_n * 16 + nt * 8 + g;
                bl2[nt][0] = kl[k0 * RSA + j0 + t];
                bl2[nt][1] = kl[k0 * RSA + j0 + 4 + t];
            }
#pragma unroll
            for (int mt = 0; mt < 2; mt++)
#pragma unroll
                for (int nt = 0; nt < 2; nt++)
                    mma_bf16(acc[mt][nt], af[mt], bl2[nt]);

#pragma unroll
            for (int mt = 0; mt < 2; mt++) {
                int r0 = warp_m * 32 + mt * 16 + g;
                af[mt][0] = ql[r0 * RSA + j0 + t];
                af[mt][1] = ql[(r0 + 8) * RSA + j0 + t];
                af[mt][2] = ql[r0 * RSA + j0 + 4 + t];
                af[mt][3] = ql[(r0 + 8) * RSA + j0 + 4 + t];
            }
#pragma unroll
            for (int mt = 0; mt < 2; mt++)
#pragma unroll
                for (int nt = 0; nt < 2; nt++)
                    mma_bf16(acc[mt][nt], af[mt], bh2[nt]);
        }

        // ---- masks + writeback (slot-indexed mask windows) ----
#pragma unroll
        for (int mt = 0; mt < 2; mt++) {
            int qq0 = warp_m * 32 + mt * 16 + g;
            int qq1 = qq0 + 8;
            int qh0 = shash_sh[n * 64 + qq0], qt0 = sidx_sh[n * 64 + qq0];
            int qh1 = shash_sh[n * 64 + qq1], qt1 = sidx_sh[n * 64 + qq1];
            int mb0 = ((qq0 + c + NC_DIM - 1) & (NC_DIM - 1)) * 64;
            int mb1 = ((qq1 + c + NC_DIM - 1) & (NC_DIM - 1)) * 64;
#pragma unroll
            for (int nt = 0; nt < 2; nt++) {
                int jj = warp_n * 16 + nt * 8 + 2 * t;
                float v00 = acc[mt][nt][0], v01 = acc[mt][nt][1];
                float v10 = acc[mt][nt][2], v11 = acc[mt][nt][3];
                if (qh0 != shash_sh[mb0 + jj])     v00 = NEG_F;
                if (qt0 == sidx_sh[mb0 + jj])      v00 = NEG_SELF_F;
                if (qh0 != shash_sh[mb0 + jj + 1]) v01 = NEG_F;
                if (qt0 == sidx_sh[mb0 + jj + 1])  v01 = NEG_SELF_F;
                if (qh1 != shash_sh[mb1 + jj])     v10 = NEG_F;
                if (qt1 == sidx_sh[mb1 + jj])      v10 = NEG_SELF_F;
                if (qh1 != shash_sh[mb1 + jj + 1]) v11 = NEG_F;
                if (qt1 == sidx_sh[mb1 + jj + 1])  v11 = NEG_SELF_F;
                *(float2*)&lg[qq0 * LGS + c * 64 + jj] = make_float2(v00, v01);
                *(float2*)&lg[qq1 * LGS + c * 64 + jj] = make_float2(v10, v11);
            }
        }
    }
    __syncthreads();

    // ---- softmax + lse: 4 threads per query row ----
    {
        const int row = tid >> 2, p = tid & 3;
        float* lrow = &lg[row * LGS];
        float m = -3.402823466e38f;
        for (int j = p; j < 192; j += 4) m = fmaxf(m, lrow[j]);
        m = fmaxf(m, __shfl_xor_sync(0xffffffffu, m, 1));
        m = fmaxf(m, __shfl_xor_sync(0xffffffffu, m, 2));
        float ssum = 0.f;
        for (int j = p; j < 192; j += 4) {
            float e = __expf(lrow[j] - m);
            lrow[j] = e;
            ssum += e;
        }
        ssum += __shfl_xor_sync(0xffffffffu, ssum, 1);
        ssum += __shfl_xor_sync(0xffffffffu, ssum, 2);
        float inv = 1.0f / ssum;
        for (int j = p; j < 192; j += 4) lrow[j] *= inv;
        if (p == 0)
            g_olse[(size_t)seg * S_DIM + sidx_sh[n * 64 + row]] = m + __logf(ssum);
    }
    __syncthreads();

    // ---- P -> bf16 hi/lo (pairs along w) ----
    {
        const int row = tid >> 2, p = tid & 3;
        const float* lrow = &lg[row * LGS];
        for (int jj = p; jj < 96; jj += 4) {
            uint32_t hh, ll;
            split2(lrow[2 * jj], lrow[2 * jj + 1], hh, ll);
            ph[row * RSP + jj] = hh;
            pl[row * RSP + jj] = ll;
        }
    }

    // ---- PV via bf16 mma: 3 chunks, Vt staged transposed (fp32 src) ----
    float oacc[2][4][4];
#pragma unroll
    for (int mt = 0; mt < 2; mt++)
#pragma unroll
        for (int nt = 0; nt < 4; nt++)
#pragma unroll
            for (int r = 0; r < 4; r++) oacc[mt][nt][r] = 0.f;

    for (int c = 0; c < 3; c++) {
        int kchunk = (n + c + NC_DIM - 1) & (NC_DIM - 1);
        __syncthreads();
#pragma unroll
        for (int i = 0; i < 4; i++) {
            int idx = i * 256 + tid;
            int wp = idx >> 5;
            int dblk = idx & 31;
            int tok0 = sidx_sh[kchunk * 64 + 2 * wp];
            int tok1 = sidx_sh[kchunk * 64 + 2 * wp + 1];
            float4 v0 = *(const float4*)&g_v[((size_t)tok0 * B_DIM + b) * E_DIM +
                                             h * D_DIM + dblk * 4];
            float4 v1 = *(const float4*)&g_v[((size_t)tok1 * B_DIM + b) * E_DIM +
                                             h * D_DIM + dblk * 4];
            float a0[4] = {v0.x, v0.y, v0.z, v0.w};
            float a1[4] = {v1.x, v1.y, v1.z, v1.w};
#pragma unroll
            for (int j = 0; j < 4; j++) {
                uint32_t hh, ll;
                split2(a0[j], a1[j], hh, ll);
                vth[(dblk * 4 + j) * RSV + wp] = hh;
                vtl[(dblk * 4 + j) * RSV + wp] = ll;
            }
        }
        __syncthreads();

#pragma unroll
        for (int ks = 0; ks < 4; ks++) {
            const int j0p = c * 32 + ks * 8;
            const int j0v = ks * 8;
            uint32_t af[2][4], bh2[4][2];
#pragma unroll
            for (int mt = 0; mt < 2; mt++) {
                int r0 = warp_m * 32 + mt * 16 + g;
                af[mt][0] = ph[r0 * RSP + j0p + t];
                af[mt][1] = ph[(r0 + 8) * RSP + j0p + t];
                af[mt][2] = ph[r0 * RSP + j0p + 4 + t];
                af[mt][3] = ph[(r0 + 8) * RSP + j0p + 4 + t];
            }
#pragma unroll
            for (int nt = 0; nt < 4; nt++) {
                int n0 = warp_n * 32 + nt * 8 + g;
                bh2[nt][0] = vth[n0 * RSV + j0v + t];
                bh2[nt][1] = vth[n0 * RSV + j0v + 4 + t];
            }
#pragma unroll
            for (int mt = 0; mt < 2; mt++)
#pragma unroll
                for (int nt = 0; nt < 4; nt++)
                    mma_bf16(oacc[mt][nt], af[mt], bh2[nt]);

            uint32_t bl2[4][2];
#pragma unroll
            for (int nt = 0; nt < 4; nt++) {
                int n0 = warp_n * 32 + nt * 8 + g;
                bl2[nt][0] = vtl[n0 * RSV + j0v + t];
                bl2[nt][1] = vtl[n0 * RSV + j0v + 4 + t];
            }
#pragma unroll
            for (int mt = 0; mt < 2; mt++)
#pragma unroll
                for (int nt = 0; nt < 4; nt++)
                    mma_bf16(oacc[mt][nt], af[mt], bl2[nt]);

#pragma unroll
            for (int mt = 0; mt < 2; mt++) {
                int r0 = warp_m * 32 + mt * 16 + g;
                af[mt][0] = pl[r0 * RSP + j0p + t];
                af[mt][1] = pl[(r0 + 8) * RSP + j0p + t];
                af[mt][2] = pl[r0 * RSP + j0p + 4 + t];
                af[mt][3] = pl[(r0 + 8) * RSP + j0p + 4 + t];
            }
#pragma unroll
            for (int mt = 0; mt < 2; mt++)
#pragma unroll
                for (int nt = 0; nt < 4; nt++)
                    mma_bf16(oacc[mt][nt], af[mt], bh2[nt]);
        }
    }

    // ---- epilogue: scatter O to original token order ----
#pragma unroll
    for (int mt = 0; mt < 2; mt++) {
        int q0 = warp_m * 32 + mt * 16 + g;
        int tok0 = sidx_sh[n * 64 + q0];
        int tok1 = sidx_sh[n * 64 + q0 + 8];
        size_t b0 = ((size_t)seg * S_DIM + tok0) * D_DIM;
        size_t b1 = ((size_t)seg * S_DIM + tok1) * D_DIM;
#pragma unroll
        for (int nt = 0; nt < 4; nt++) {
            int d0 = warp_n * 32 + nt * 8 + 2 * t;
            *(float2*)&g_oout[b0 + d0] = make_float2(oacc[mt][nt][0], oacc[mt][nt][1]);
            *(float2*)&g_oout[b1 + d0] = make_float2(oacc[mt][nt][2], oacc[mt][nt][3]);
        }
    }
}

// ------- combine rounds by softmax over lse; writes bf16 hi/lo directly ----
__global__ void combine_kernel()
{
    const int g = blockIdx.x * 256 + threadIdx.x;
    const int flat = g * 4;
    const int e = flat & (E_DIM - 1);
    const int sb = flat >> 10;
    const int b = sb & 1;
    const int s = sb >> 1;
    const int h = e >> 7;
    const int d = e & 127;

    const int seg0 = (b * R_DIM + 0) * H_DIM + h;
    const int seg1 = (b * R_DIM + 1) * H_DIM + h;

    float l0 = g_olse[(size_t)seg0 * S_DIM + s];
    float l1 = g_olse[(size_t)seg1 * S_DIM + s];
    float m = fmaxf(l0, l1);
    float e0 = __expf(l0 - m), e1 = __expf(l1 - m);
    float inv = 1.0f / (e0 + e1);
    float w0 = e0 * inv, w1 = e1 * inv;

    float4 o0 = *(const float4*)&g_oout[((size_t)seg0 * S_DIM + s) * D_DIM + d];
    float4 o1 = *(const float4*)&g_oout[((size_t)seg1 * S_DIM + s) * D_DIM + d];
    float4 r;
    r.x = w0 * o0.x + w1 * o1.x;
    r.y = w0 * o0.y + w1 * o1.y;
    r.z = w0 * o0.z + w1 * o1.z;
    r.w = w0 * o0.w + w1 * o1.w;
    uint2 hh, ll;
    split2(r.x, r.y, hh.x, ll.x);
    split2(r.z, r.w, hh.y, ll.y);
    ((uint2*)g_och)[g] = hh;
    ((uint2*)g_ocl)[g] = ll;
}

// ---------------- launcher ----------------
extern "C" void kernel_launch(void* const* d_in, const int* in_sizes, int n_in,
                              void* d_out, int out_size)
{
    const float* x      = (const float*)d_in[0];
    const float* wq     = (const float*)d_in[1];
    const float* bq     = (const float*)d_in[2];
    const float* wv     = (const float*)d_in[3];
    const float* bv     = (const float*)d_in[4];
    const float* wo     = (const float*)d_in[5];
    const float* bo     = (const float*)d_in[6];
    const float* hash_w = (const float*)d_in[7];
    float* out = (float*)d_out;

    float *p_qraw, *p_v;
    uint32_t *p_xh, *p_xl, *p_wvh, *p_wvl, *p_woh, *p_wol, *p_och, *p_ocl;
    cudaGetSymbolAddress((void**)&p_qraw, g_qraw);
    cudaGetSymbolAddress((void**)&p_v,    g_v);
    cudaGetSymbolAddress((void**)&p_xh,  g_xh);  cudaGetSymbolAddress((void**)&p_xl,  g_xl);
    cudaGetSymbolAddress((void**)&p_wvh, g_wvh); cudaGetSymbolAddress((void**)&p_wvl, g_wvl);
    cudaGetSymbolAddress((void**)&p_woh, g_woh); cudaGetSymbolAddress((void**)&p_wol, g_wol);
    cudaGetSymbolAddress((void**)&p_och, g_och); cudaGetSymbolAddress((void**)&p_ocl, g_ocl);

    cudaFuncSetAttribute(attn_kernel, cudaFuncAttributeMaxDynamicSharedMemorySize,
                         ATTN_SMEM);
    cudaFuncSetAttribute(gemm_bf16_kernel,
                         cudaFuncAttributeMaxDynamicSharedMemorySize, BGEMM_SMEM);

    dim3 gemm_grid(E_DIM / 128, MROWS / 128);
    const int nsplit = N4X + 2 * N4W;

    // pre-split x, wv, wo for bf16 GEMMs (one merged launch)
    split_all_kernel<<<(nsplit + 255) / 256, 256>>>((const float4*)x,
                                                    (const float4*)wv,
                                                    (const float4*)wo);
    // q: SIMT fp32 (flip-free); v: bf16 mma split (fp32 output)
    gemm_bias_kernel<<<gemm_grid, 256>>>(x, wq, bq, p_qraw, MROWS, E_DIM, E_DIM);
    gemm_bf16_kernel<<<gemm_grid, 256, BGEMM_SMEM>>>(p_xh, p_xl, p_wvh, p_wvl,
                                                     bv, p_v, MROWS, E_DIM, E_DIM);
    norm_split_kernel<<<MROWS, 256>>>();
    hash_kernel<<<dim3(S_DIM / 256, B_DIM * H_DIM), 256>>>(hash_w);
    sort_kernel<<<NSEG, 512>>>();
    attn_kernel<<<NSEG * NC_DIM, 256, ATTN_SMEM>>>();
    combine_kernel<<<MROWS * E_DIM / 4 / 256, 256>>>();
    gemm_bf16_kernel<<<gemm_grid, 256, BGEMM_SMEM>>>(p_och, p_ocl, p_woh, p_wol,
                                                     bo, out, MROWS, E_DIM, E_DIM);
}

// round 16
// speedup vs baseline: 1.1221x; 1.0026x over previous
#include <cuda_runtime.h>
#include <cuda_bf16.h>
#include <math.h>
#include <stdint.h>

// ---------------- problem dims ----------------
#define S_DIM 4096
#define B_DIM 2
#define E_DIM 1024
#define H_DIM 8
#define R_DIM 2
#define C_DIM 64
#define D_DIM 128
#define NC_DIM 64                    // S / C
#define NSEG (B_DIM*R_DIM*H_DIM)     // 32
#define MROWS (S_DIM*B_DIM)          // 8192
#define SCALE_F 0.08838834764831845f // D^-0.5
#define NEG_F (-1e9f)
#define NEG_SELF_F (-1e5f)

// ---------------- scratch (device globals; no allocation) ----------------
__device__ float g_qraw[MROWS*E_DIM];     // x@wq^T + bq (fp32, feeds hash)
__device__ float g_v[MROWS*E_DIM];        // x@wv^T + bv
__device__ float g_oout[NSEG*S_DIM*D_DIM];
__device__ float g_olse[NSEG*S_DIM];
__device__ int   g_hash[NSEG*S_DIM];
__device__ int   g_sidx[NSEG*S_DIM];
__device__ int   g_shash[NSEG*S_DIM];
// pre-split bf16 hi/lo (u32 = bf16x2 pairs along last dim)
__device__ uint32_t g_xh[MROWS*E_DIM/2], g_xl[MROWS*E_DIM/2];
__device__ uint32_t g_wvh[E_DIM*E_DIM/2], g_wvl[E_DIM*E_DIM/2];
__device__ uint32_t g_woh[E_DIM*E_DIM/2], g_wol[E_DIM*E_DIM/2];
__device__ uint32_t g_och[MROWS*E_DIM/2], g_ocl[MROWS*E_DIM/2]; // combined o
__device__ uint32_t g_qsh[MROWS*E_DIM/2], g_qsl[MROWS*E_DIM/2]; // scaled q
__device__ uint32_t g_kbh[MROWS*E_DIM/2], g_kbl[MROWS*E_DIM/2]; // normalized k

// ---------------- bf16 split helpers ----------------
__device__ __forceinline__ void split2(float a, float b, uint32_t& h, uint32_t& l) {
    __nv_bfloat162 hh = __floats2bfloat162_rn(a, b);
    h = *reinterpret_cast<uint32_t*>(&hh);
    __nv_bfloat162 ll = __floats2bfloat162_rn(a - __bfloat162float(hh.x),
                                              b - __bfloat162float(hh.y));
    l = *reinterpret_cast<uint32_t*>(&ll);
}

__device__ __forceinline__ void mma_bf16(float* d, const uint32_t* a,
                                         const uint32_t* b) {
    asm volatile(
        "mma.sync.aligned.m16n8k16.row.col.f32.bf16.bf16.f32 "
        "{%0,%1,%2,%3}, {%4,%5,%6,%7}, {%8,%9}, {%0,%1,%2,%3};\n"
        : "+f"(d[0]), "+f"(d[1]), "+f"(d[2]), "+f"(d[3])
        : "r"(a[0]), "r"(a[1]), "r"(a[2]), "r"(a[3]), "r"(b[0]), "r"(b[1]));
}

// ---------------- merged split conversion kernel (memory-bound) --------
#define N4X (MROWS*E_DIM/4)
#define N4W (E_DIM*E_DIM/4)
__global__ void split_all_kernel(const float4* __restrict__ x,
                                 const float4* __restrict__ wv,
                                 const float4* __restrict__ wo)
{
    int i = blockIdx.x * 256 + threadIdx.x;
    const float4* src; uint2 *dh, *dl; int j;
    if (i < N4X) {
        src = x; dh = (uint2*)g_xh; dl = (uint2*)g_xl; j = i;
    } else if (i < N4X + N4W) {
        src = wv; dh = (uint2*)g_wvh; dl = (uint2*)g_wvl; j = i - N4X;
    } else {
        src = wo; dh = (uint2*)g_woh; dl = (uint2*)g_wol; j = i - N4X - N4W;
    }
    float4 v = src[j];
    uint2 h, l;
    split2(v.x, v.y, h.x, l.x);
    split2(v.z, v.w, h.y, l.y);
    dh[j] = h; dl[j] = l;
}

// =====================================================================
// SIMT fp32 GEMM (q projection ONLY — flip-free path).
// v2: manual register double-buffering of per-k fragments to break the
// LDS->FFMA dependency stall chain. Per-element FMA order unchanged
// (k-ascending) -> bit-exact vs previous rounds.
// =====================================================================
__global__ void __launch_bounds__(256)
gemm_bias_kernel(const float* __restrict__ A,
                 const float* __restrict__ W,
                 const float* __restrict__ bias,
                 float* __restrict__ C,
                 int M, int N, int K)
{
    __shared__ float As[2][16][132];
    __shared__ float Ws[2][16][132];

    const int tid = threadIdx.x;
    const int bm = blockIdx.y * 128;
    const int bn = blockIdx.x * 128;
    const int tm = tid >> 4;
    const int tn = tid & 15;

    float acc[8][8];
#pragma unroll
    for (int i = 0; i < 8; i++)
#pragma unroll
        for (int j = 0; j < 8; j++) acc[i][j] = 0.f;

    float4 ha[2], hw[2];

#define GLD(k0)                                                            \
    {                                                                      \
        _Pragma("unroll")                                                  \
        for (int it = 0; it < 2; it++) {                                   \
            int l = it * 256 + tid; int m = l >> 2; int kq = (l & 3) * 4;  \
            ha[it] = *(const float4*)&A[(size_t)(bm + m) * K + (k0) + kq]; \
            hw[it] = *(const float4*)&W[(size_t)(bn + m) * K + (k0) + kq]; \
        }                                                                  \
    }
#define GST(nb)                                                            \
    {                                                                      \
        _Pragma("unroll")                                                  \
        for (int it = 0; it < 2; it++) {                                   \
            int l = it * 256 + tid; int m = l >> 2; int kq = (l & 3) * 4;  \
            As[nb][kq + 0][m] = ha[it].x; As[nb][kq + 1][m] = ha[it].y;    \
            As[nb][kq + 2][m] = ha[it].z; As[nb][kq + 3][m] = ha[it].w;    \
            Ws[nb][kq + 0][m] = hw[it].x; Ws[nb][kq + 1][m] = hw[it].y;    \
            Ws[nb][kq + 2][m] = hw[it].z; Ws[nb][kq + 3][m] = hw[it].w;    \
        }                                                                  \
    }

    GLD(0); GST(0); __syncthreads();

    const int nIter = K >> 4;
    for (int ii = 0; ii < nIter; ii++) {
        if (ii + 1 < nIter) GLD((ii + 1) << 4);
        const int cb = ii & 1;

        // register double-buffered fragments over k
        float4 a0c = *(const float4*)&As[cb][0][tm * 8];
        float4 a1c = *(const float4*)&As[cb][0][tm * 8 + 4];
        float4 b0c = *(const float4*)&Ws[cb][0][tn * 8];
        float4 b1c = *(const float4*)&Ws[cb][0][tn * 8 + 4];
#pragma unroll
        for (int k = 0; k < 16; k++) {
            float4 a0n, a1n, b0n, b1n;
            if (k < 15) {
                a0n = *(const float4*)&As[cb][k + 1][tm * 8];
                a1n = *(const float4*)&As[cb][k + 1][tm * 8 + 4];
                b0n = *(const float4*)&Ws[cb][k + 1][tn * 8];
                b1n = *(const float4*)&Ws[cb][k + 1][tn * 8 + 4];
            }
            float av[8] = {a0c.x, a0c.y, a0c.z, a0c.w, a1c.x, a1c.y, a1c.z, a1c.w};
            float bv[8] = {b0c.x, b0c.y, b0c.z, b0c.w, b1c.x, b1c.y, b1c.z, b1c.w};
#pragma unroll
            for (int i = 0; i < 8; i++)
#pragma unroll
                for (int j = 0; j < 8; j++) acc[i][j] += av[i] * bv[j];
            if (k < 15) { a0c = a0n; a1c = a1n; b0c = b0n; b1c = b1n; }
        }
        if (ii + 1 < nIter) GST((ii + 1) & 1);
        __syncthreads();
    }
#undef GLD
#undef GST

    float4 bb0 = *(const float4*)&bias[bn + tn * 8];
    float4 bb1 = *(const float4*)&bias[bn + tn * 8 + 4];
#pragma unroll
    for (int i = 0; i < 8; i++) {
        float4 o0, o1;
        o0.x = acc[i][0] + bb0.x; o0.y = acc[i][1] + bb0.y;
        o0.z = acc[i][2] + bb0.z; o0.w = acc[i][3] + bb0.w;
        o1.x = acc[i][4] + bb1.x; o1.y = acc[i][5] + bb1.y;
        o1.z = acc[i][6] + bb1.z; o1.w = acc[i][7] + bb1.w;
        size_t rowoff = (size_t)(bm + tm * 8 + i) * N + bn + tn * 8;
        *(float4*)&C[rowoff]     = o0;
        *(float4*)&C[rowoff + 4] = o1;
    }
}

// =====================================================================
// bf16 mma split GEMM with PRE-CONVERTED hi/lo inputs (v/o projections).
// =====================================================================
#define RS 20
#define BGEMM_SMEM (2 * 4 * 128 * RS * 4)

__global__ void __launch_bounds__(256)
gemm_bf16_kernel(const uint32_t* __restrict__ Ah, const uint32_t* __restrict__ Al,
                 const uint32_t* __restrict__ Wh, const uint32_t* __restrict__ Wl,
                 const float* __restrict__ bias, float* __restrict__ C,
                 int M, int N, int K)
{
    extern __shared__ uint32_t bsm[];
    uint32_t* base[2];
    base[0] = bsm;
    base[1] = bsm + 4 * 128 * RS;

    const int tid = threadIdx.x;
    const int wid = tid >> 5, lane = tid & 31;
    const int g = lane >> 2, t = lane & 3;
    const int warp_m = wid & 1;
    const int warp_n = wid >> 1;
    const int bm = blockIdx.y * 128, bn = blockIdx.x * 128;
    const int K2 = K >> 1;

    float acc[4][4][4];
#pragma unroll
    for (int mi = 0; mi < 4; mi++)
#pragma unroll
        for (int ni = 0; ni < 4; ni++)
#pragma unroll
            for (int r = 0; r < 4; r++) acc[mi][ni][r] = 0.f;

    uint4 rah[2], ral[2], rwh[2], rwl[2];

#define BGLD(k02)                                                            \
    {                                                                        \
        _Pragma("unroll")                                                    \
        for (int it = 0; it < 2; it++) {                                     \
            int task = it * 256 + tid; int row = task >> 2; int q4 = task & 3;\
            size_t oa = (size_t)(bm + row) * K2 + (k02) + q4 * 4;            \
            size_t ow = (size_t)(bn + row) * K2 + (k02) + q4 * 4;            \
            rah[it] = *(const uint4*)&Ah[oa]; ral[it] = *(const uint4*)&Al[oa];\
            rwh[it] = *(const uint4*)&Wh[ow]; rwl[it] = *(const uint4*)&Wl[ow];\
        }                                                                    \
    }
#define BGST(nb)                                                             \
    {                                                                        \
        uint32_t* sAh = base[nb];                                            \
        uint32_t* sAl = sAh + 128 * RS;                                      \
        uint32_t* sBh = sAl + 128 * RS;                                      \
        uint32_t* sBl = sBh + 128 * RS;                                      \
        _Pragma("unroll")                                                    \
        for (int it = 0; it < 2; it++) {                                     \
            int task = it * 256 + tid; int row = task >> 2; int q4 = task & 3;\
            int off = row * RS + q4 * 4;                                     \
            *(uint4*)&sAh[off] = rah[it]; *(uint4*)&sAl[off] = ral[it];      \
            *(uint4*)&sBh[off] = rwh[it]; *(uint4*)&sBl[off] = rwl[it];      \
        }                                                                    \
    }

    BGLD(0); BGST(0); __syncthreads();

    const int nIter = K >> 5;
    for (int ii = 0; ii < nIter; ii++) {
        if (ii + 1 < nIter) BGLD((ii + 1) * 16);
        const uint32_t* Ahs = base[ii & 1];
        const uint32_t* Als = Ahs + 128 * RS;
        const uint32_t* Bhs = Als + 128 * RS;
        const uint32_t* Bls = Bhs + 128 * RS;

#pragma unroll
        for (int s = 0; s < 2; s++) {
            const int j0 = s * 8;
            uint32_t af[4][4], bh[4][2];
#pragma unroll
            for (int mi = 0; mi < 4; mi++) {
                int r0 = warp_m * 64 + mi * 16 + g;
                af[mi][0] = Ahs[r0 * RS + j0 + t];
                af[mi][1] = Ahs[(r0 + 8) * RS + j0 + t];
                af[mi][2] = Ahs[r0 * RS + j0 + 4 + t];
                af[mi][3] = Ahs[(r0 + 8) * RS + j0 + 4 + t];
            }
#pragma unroll
            for (int ni = 0; ni < 4; ni++) {
                int n0 = warp_n * 32 + ni * 8 + g;
                bh[ni][0] = Bhs[n0 * RS + j0 + t];
                bh[ni][1] = Bhs[n0 * RS + j0 + 4 + t];
            }
#pragma unroll
            for (int mi = 0; mi < 4; mi++)
#pragma unroll
                for (int ni = 0; ni < 4; ni++)
                    mma_bf16(acc[mi][ni], af[mi], bh[ni]);

            uint32_t bl[4][2];
#pragma unroll
            for (int ni = 0; ni < 4; ni++) {
                int n0 = warp_n * 32 + ni * 8 + g;
                bl[ni][0] = Bls[n0 * RS + j0 + t];
                bl[ni][1] = Bls[n0 * RS + j0 + 4 + t];
            }
#pragma unroll
            for (int mi = 0; mi < 4; mi++)
#pragma unroll
                for (int ni = 0; ni < 4; ni++)
                    mma_bf16(acc[mi][ni], af[mi], bl[ni]);

#pragma unroll
            for (int mi = 0; mi < 4; mi++) {
                int r0 = warp_m * 64 + mi * 16 + g;
                af[mi][0] = Als[r0 * RS + j0 + t];
                af[mi][1] = Als[(r0 + 8) * RS + j0 + t];
                af[mi][2] = Als[r0 * RS + j0 + 4 + t];
                af[mi][3] = Als[(r0 + 8) * RS + j0 + 4 + t];
            }
#pragma unroll
            for (int mi = 0; mi < 4; mi++)
#pragma unroll
                for (int ni = 0; ni < 4; ni++)
                    mma_bf16(acc[mi][ni], af[mi], bh[ni]);
        }
        if (ii + 1 < nIter) BGST((ii + 1) & 1);
        __syncthreads();
    }
#undef BGLD
#undef BGST

#pragma unroll
    for (int mi = 0; mi < 4; mi++) {
        int row0 = bm + warp_m * 64 + mi * 16 + g;
#pragma unroll
        for (int ni = 0; ni < 4; ni++) {
            int col = bn + warp_n * 32 + ni * 8 + 2 * t;
            float b0 = bias[col], b1 = bias[col + 1];
            *(float2*)&C[(size_t)row0 * N + col] =
                make_float2(acc[mi][ni][0] + b0, acc[mi][ni][1] + b1);
            *(float2*)&C[(size_t)(row0 + 8) * N + col] =
                make_float2(acc[mi][ni][2] + b0, acc[mi][ni][3] + b1);
        }
    }
}

// ---------------- fused norm + split: k = q/||q|| and qs = q*SCALE ----
__global__ void norm_split_kernel()
{
    const int row = blockIdx.x;
    const int tid = threadIdx.x;      // 256
    const float4* q4 = (const float4*)(g_qraw + (size_t)row * E_DIM);
    float4 v = q4[tid];
    float ss = v.x * v.x + v.y * v.y + v.z * v.z + v.w * v.w;
#pragma unroll
    for (int o = 16; o > 0; o >>= 1) ss += __shfl_xor_sync(0xffffffffu, ss, o);
    __shared__ float red[8];
    __shared__ float s_inv;
    if ((tid & 31) == 0) red[tid >> 5] = ss;
    __syncthreads();
    if (tid == 0) {
        float tt = 0.f;
#pragma unroll
        for (int i = 0; i < 8; i++) tt += red[i];
        s_inv = 1.0f / sqrtf(tt);
    }
    __syncthreads();
    const float inv = s_inv;

    const int idx = row * 256 + tid;  // uint2 index
    uint2 h, l;
    split2(v.x * inv, v.y * inv, h.x, l.x);
    split2(v.z * inv, v.w * inv, h.y, l.y);
    ((uint2*)g_kbh)[idx] = h; ((uint2*)g_kbl)[idx] = l;
    split2(v.x * SCALE_F, v.y * SCALE_F, h.x, l.x);
    split2(v.z * SCALE_F, v.w * SCALE_F, h.y, l.y);
    ((uint2*)g_qsh)[idx] = h; ((uint2*)g_qsl)[idx] = l;
}

// ---------------- LSH hashing: both rounds fused (verified win) -------
__global__ void hash_kernel(const float* __restrict__ hash_w)
{
    const int bh = blockIdx.y;               // b*H + h
    const int b = bh / H_DIM;
    const int h = bh % H_DIM;

    __shared__ float hw[2][D_DIM * 8];
    for (int r = 0; r < 2; r++) {
        const float* hwp = hash_w + (size_t)(r * H_DIM + h) * D_DIM * 8;
        for (int i = threadIdx.x; i < D_DIM * 8; i += 256) hw[r][i] = hwp[i];
    }
    __syncthreads();

    const int s = blockIdx.x * 256 + threadIdx.x;
    const float4* qp4 = (const float4*)(g_qraw +
                        ((size_t)s * B_DIM + b) * E_DIM + h * D_DIM);

    float acc[2][8];
#pragma unroll
    for (int r = 0; r < 2; r++)
#pragma unroll
        for (int m = 0; m < 8; m++) acc[r][m] = 0.f;

    for (int d4 = 0; d4 < 32; d4++) {
        float4 qv = qp4[d4];
#pragma unroll
        for (int r = 0; r < 2; r++) {
            const float* h0 = &hw[r][(d4 * 4 + 0) * 8];
            const float* h1 = &hw[r][(d4 * 4 + 1) * 8];
            const float* h2 = &hw[r][(d4 * 4 + 2) * 8];
            const float* h3 = &hw[r][(d4 * 4 + 3) * 8];
#pragma unroll
            for (int m = 0; m < 8; m++) {
                acc[r][m] += qv.x * h0[m];
                acc[r][m] += qv.y * h1[m];
                acc[r][m] += qv.z * h2[m];
                acc[r][m] += qv.w * h3[m];
            }
        }
    }
#pragma unroll
    for (int r = 0; r < 2; r++) {
        float best = acc[r][0]; int bi = 0;
#pragma unroll
        for (int m = 1; m < 8; m++) if (acc[r][m] > best) { best = acc[r][m]; bi = m; }
#pragma unroll
        for (int m = 0; m < 8; m++) if (-acc[r][m] > best) { best = -acc[r][m]; bi = 8 + m; }
        int seg = (b * R_DIM + r) * H_DIM + h;
        g_hash[(size_t)seg * S_DIM + s] = bi;
    }
}

// ---------------- stable counting sort (16 buckets) ----------------
__global__ void sort_kernel()
{
    const int seg = blockIdx.x;
    const int tid = threadIdx.x;
    __shared__ int tc[512][16];
    __shared__ int base[16], tot[16];

    const int* hp = g_hash + (size_t)seg * S_DIM;
#pragma unroll
    for (int m = 0; m < 16; m++) tc[tid][m] = 0;
    int myh[8];
#pragma unroll
    for (int i = 0; i < 8; i++) {
        myh[i] = hp[tid * 8 + i];
        tc[tid][myh[i]]++;
    }
    __syncthreads();
    if (tid < 16) {
        int run = 0;
        for (int t = 0; t < 512; t++) { int v = tc[t][tid]; tc[t][tid] = run; run += v; }
        tot[tid] = run;
    }
    __syncthreads();
    if (tid == 0) {
        int run = 0;
#pragma unroll
        for (int m = 0; m < 16; m++) { base[m] = run; run += tot[m]; }
    }
    __syncthreads();
#pragma unroll
    for (int i = 0; i < 8; i++) {
        int hh = myh[i];
        int pos = base[hh] + tc[tid][hh];
        tc[tid][hh]++;
        g_sidx[(size_t)seg * S_DIM + pos]  = tid * 8 + i;
        g_shash[(size_t)seg * S_DIM + pos] = hh;
    }
}

// ---------------- chunked LSH attention: QK and PV via bf16 mma ------
#define LGS 196
#define RSA 68    // u32 stride for QK 64-row tiles
#define RSP 100   // u32 stride for P rows (96 pairs + pad)
#define RSV 33    // u32 stride for Vt rows (32 pairs + pad)
#define UN_U32 (2*64*RSP + 2*128*RSV)   // >= QK's 4*64*RSA
#define ATTN_SMEM ((64*LGS + UN_U32 + 2*S_DIM) * 4)

__global__ void __launch_bounds__(256) attn_kernel()
{
    extern __shared__ float sm[];
    float* lg = sm;                               // [64][LGS] fp32
    uint32_t* un = (uint32_t*)(sm + 64 * LGS);    // union region
    uint32_t* qh = un;                            // [64][RSA]
    uint32_t* ql = un + 64 * RSA;
    uint32_t* kh = un + 2 * 64 * RSA;
    uint32_t* kl = un + 3 * 64 * RSA;
    uint32_t* ph  = un;                           // [64][RSP]
    uint32_t* pl  = un + 64 * RSP;
    uint32_t* vth = un + 2 * 64 * RSP;            // [128][RSV]
    uint32_t* vtl = vth + 128 * RSV;
    int* sidx_sh  = (int*)(sm + 64 * LGS + UN_U32);
    int* shash_sh = sidx_sh + S_DIM;

    const int bid = blockIdx.x;
    const int n   = bid % NC_DIM;
    const int seg = bid / NC_DIM;
    const int b   = seg / (R_DIM * H_DIM);
    const int h   = seg % H_DIM;
    const int tid = threadIdx.x;
    const int wid = tid >> 5, lane = tid & 31;
    const int g = lane >> 2, t = lane & 3;
    const int warp_m = wid & 1, warp_n = wid >> 1;

    const int* gsidx  = g_sidx  + (size_t)seg * S_DIM;
    const int* gshash = g_shash + (size_t)seg * S_DIM;
    for (int i = tid; i < S_DIM; i += 256) {
        sidx_sh[i]  = gsidx[i];
        shash_sh[i] = gshash[i];
    }
    __syncthreads();

    // ---- stage q hi/lo (pre-scaled, pre-split) ----
#pragma unroll
    for (int i = 0; i < 4; i++) {
        int f = i * 256 + tid; int row = f >> 4; int c16 = f & 15;
        int tok = sidx_sh[n * 64 + row];
        size_t rb = ((size_t)tok * B_DIM + b) * (E_DIM / 2) + h * (D_DIM / 2);
        *(uint4*)&qh[row * RSA + c16 * 4] = *(const uint4*)&g_qsh[rb + c16 * 4];
        *(uint4*)&ql[row * RSA + c16 * 4] = *(const uint4*)&g_qsl[rb + c16 * 4];
    }

    // ---- QK logits via mma: 3 chunks ----
    for (int c = 0; c < 3; c++) {
        int kchunk = (n + c + NC_DIM - 1) & (NC_DIM - 1);
        __syncthreads();
#pragma unroll
        for (int i = 0; i < 4; i++) {
            int f = i * 256 + tid; int row = f >> 4; int c16 = f & 15;
            int tok = sidx_sh[kchunk * 64 + row];
            size_t rb = ((size_t)tok * B_DIM + b) * (E_DIM / 2) + h * (D_DIM / 2);
            *(uint4*)&kh[row * RSA + c16 * 4] = *(const uint4*)&g_kbh[rb + c16 * 4];
            *(uint4*)&kl[row * RSA + c16 * 4] = *(const uint4*)&g_kbl[rb + c16 * 4];
        }
        __syncthreads();

        float acc[2][2][4];
#pragma unroll
        for (int mt = 0; mt < 2; mt++)
#pragma unroll
            for (int nt = 0; nt < 2; nt++)
#pragma unroll
                for (int r = 0; r < 4; r++) acc[mt][nt][r] = 0.f;

#pragma unroll
        for (int ks = 0; ks < 8; ks++) {
            const int j0 = ks * 8;
            uint32_t af[2][4], bh2[2][2];
#pragma unroll
            for (int mt = 0; mt < 2; mt++) {
                int r0 = warp_m * 32 + mt * 16 + g;
                af[mt][0] = qh[r0 * RSA + j0 + t];
                af[mt][1] = qh[(r0 + 8) * RSA + j0 + t];
                af[mt][2] = qh[r0 * RSA + j0 + 4 + t];
                af[mt][3] = qh[(r0 + 8) * RSA + j0 + 4 + t];
            }
#pragma unroll
            for (int nt = 0; nt < 2; nt++) {
                int k0 = warp_n * 16 + nt * 8 + g;
                bh2[nt][0] = kh[k0 * RSA + j0 + t];
                bh2[nt][1] = kh[k0 * RSA + j0 + 4 + t];
            }
#pragma unroll
            for (int mt = 0; mt < 2; mt++)
#pragma unroll
                for (int nt = 0; nt < 2; nt++)
                    mma_bf16(acc[mt][nt], af[mt], bh2[nt]);

            uint32_t bl2[2][2];
#pragma unroll
            for (int nt = 0; nt < 2; nt++) {
                int k0 = warp_n * 16 + nt * 8 + g;
                bl2[nt][0] = kl[k0 * RSA + j0 + t];
                bl2[nt][1] = kl[k0 * RSA + j0 + 4 + t];
            }
#pragma unroll
            for (int mt = 0; mt < 2; mt++)
#pragma unroll
                for (int nt = 0; nt < 2; nt++)
                    mma_bf16(acc[mt][nt], af[mt], bl2[nt]);

#pragma unroll
            for (int mt = 0; mt < 2; mt++) {
                int r0 = warp_m * 32 + mt * 16 + g;
                af[mt][0] = ql[r0 * RSA + j0 + t];
                af[mt][1] = ql[(r0 + 8) * RSA + j0 + t];
                af[mt][2] = ql[r0 * RSA + j0 + 4 + t];
                af[mt][3] = ql[(r0 + 8) * RSA + j0 + 4 + t];
            }
#pragma unroll
            for (int mt = 0; mt < 2; mt++)
#pragma unroll
                for (int nt = 0; nt < 2; nt++)
                    mma_bf16(acc[mt][nt], af[mt], bh2[nt]);
        }

        // ---- masks + writeback (slot-indexed mask windows) ----
#pragma unroll
        for (int mt = 0; mt < 2; mt++) {
            int qq0 = warp_m * 32 + mt * 16 + g;
            int qq1 = qq0 + 8;
            int qh0 = shash_sh[n * 64 + qq0], qt0 = sidx_sh[n * 64 + qq0];
            int qh1 = shash_sh[n * 64 + qq1], qt1 = sidx_sh[n * 64 + qq1];
            int mb0 = ((qq0 + c + NC_DIM - 1) & (NC_DIM - 1)) * 64;
            int mb1 = ((qq1 + c + NC_DIM - 1) & (NC_DIM - 1)) * 64;
#pragma unroll
            for (int nt = 0; nt < 2; nt++) {
                int jj = warp_n * 16 + nt * 8 + 2 * t;
                float v00 = acc[mt][nt][0], v01 = acc[mt][nt][1];
                float v10 = acc[mt][nt][2], v11 = acc[mt][nt][3];
                if (qh0 != shash_sh[mb0 + jj])     v00 = NEG_F;
                if (qt0 == sidx_sh[mb0 + jj])      v00 = NEG_SELF_F;
                if (qh0 != shash_sh[mb0 + jj + 1]) v01 = NEG_F;
                if (qt0 == sidx_sh[mb0 + jj + 1])  v01 = NEG_SELF_F;
                if (qh1 != shash_sh[mb1 + jj])     v10 = NEG_F;
                if (qt1 == sidx_sh[mb1 + jj])      v10 = NEG_SELF_F;
                if (qh1 != shash_sh[mb1 + jj + 1]) v11 = NEG_F;
                if (qt1 == sidx_sh[mb1 + jj + 1])  v11 = NEG_SELF_F;
                *(float2*)&lg[qq0 * LGS + c * 64 + jj] = make_float2(v00, v01);
                *(float2*)&lg[qq1 * LGS + c * 64 + jj] = make_float2(v10, v11);
            }
        }
    }
    __syncthreads();

    // ---- softmax + lse: 4 threads per query row ----
    {
        const int row = tid >> 2, p = tid & 3;
        float* lrow = &lg[row * LGS];
        float m = -3.402823466e38f;
        for (int j = p; j < 192; j += 4) m = fmaxf(m, lrow[j]);
        m = fmaxf(m, __shfl_xor_sync(0xffffffffu, m, 1));
        m = fmaxf(m, __shfl_xor_sync(0xffffffffu, m, 2));
        float ssum = 0.f;
        for (int j = p; j < 192; j += 4) {
            float e = __expf(lrow[j] - m);
            lrow[j] = e;
            ssum += e;
        }
        ssum += __shfl_xor_sync(0xffffffffu, ssum, 1);
        ssum += __shfl_xor_sync(0xffffffffu, ssum, 2);
        float inv = 1.0f / ssum;
        for (int j = p; j < 192; j += 4) lrow[j] *= inv;
        if (p == 0)
            g_olse[(size_t)seg * S_DIM + sidx_sh[n * 64 + row]] = m + __logf(ssum);
    }
    __syncthreads();

    // ---- P -> bf16 hi/lo (pairs along w) ----
    {
        const int row = tid >> 2, p = tid & 3;
        const float* lrow = &lg[row * LGS];
        for (int jj = p; jj < 96; jj += 4) {
            uint32_t hh, ll;
            split2(lrow[2 * jj], lrow[2 * jj + 1], hh, ll);
            ph[row * RSP + jj] = hh;
            pl[row * RSP + jj] = ll;
        }
    }

    // ---- PV via bf16 mma: 3 chunks, Vt staged transposed (fp32 src) ----
    float oacc[2][4][4];
#pragma unroll
    for (int mt = 0; mt < 2; mt++)
#pragma unroll
        for (int nt = 0; nt < 4; nt++)
#pragma unroll
            for (int r = 0; r < 4; r++) oacc[mt][nt][r] = 0.f;

    for (int c = 0; c < 3; c++) {
        int kchunk = (n + c + NC_DIM - 1) & (NC_DIM - 1);
        __syncthreads();
#pragma unroll
        for (int i = 0; i < 4; i++) {
            int idx = i * 256 + tid;
            int wp = idx >> 5;
            int dblk = idx & 31;
            int tok0 = sidx_sh[kchunk * 64 + 2 * wp];
            int tok1 = sidx_sh[kchunk * 64 + 2 * wp + 1];
            float4 v0 = *(const float4*)&g_v[((size_t)tok0 * B_DIM + b) * E_DIM +
                                             h * D_DIM + dblk * 4];
            float4 v1 = *(const float4*)&g_v[((size_t)tok1 * B_DIM + b) * E_DIM +
                                             h * D_DIM + dblk * 4];
            float a0[4] = {v0.x, v0.y, v0.z, v0.w};
            float a1[4] = {v1.x, v1.y, v1.z, v1.w};
#pragma unroll
            for (int j = 0; j < 4; j++) {
                uint32_t hh, ll;
                split2(a0[j], a1[j], hh, ll);
                vth[(dblk * 4 + j) * RSV + wp] = hh;
                vtl[(dblk * 4 + j) * RSV + wp] = ll;
            }
        }
        __syncthreads();

#pragma unroll
        for (int ks = 0; ks < 4; ks++) {
            const int j0p = c * 32 + ks * 8;
            const int j0v = ks * 8;
            uint32_t af[2][4], bh2[4][2];
#pragma unroll
            for (int mt = 0; mt < 2; mt++) {
                int r0 = warp_m * 32 + mt * 16 + g;
                af[mt][0] = ph[r0 * RSP + j0p + t];
                af[mt][1] = ph[(r0 + 8) * RSP + j0p + t];
                af[mt][2] = ph[r0 * RSP + j0p + 4 + t];
                af[mt][3] = ph[(r0 + 8) * RSP + j0p + 4 + t];
            }
#pragma unroll
            for (int nt = 0; nt < 4; nt++) {
                int n0 = warp_n * 32 + nt * 8 + g;
                bh2[nt][0] = vth[n0 * RSV + j0v + t];
                bh2[nt][1] = vth[n0 * RSV + j0v + 4 + t];
            }
#pragma unroll
            for (int mt = 0; mt < 2; mt++)
#pragma unroll
                for (int nt = 0; nt < 4; nt++)
                    mma_bf16(oacc[mt][nt], af[mt], bh2[nt]);

            uint32_t bl2[4][2];
#pragma unroll
            for (int nt = 0; nt < 4; nt++) {
                int n0 = warp_n * 32 + nt * 8 + g;
                bl2[nt][0] = vtl[n0 * RSV + j0v + t];
                bl2[nt][1] = vtl[n0 * RSV + j0v + 4 + t];
            }
#pragma unroll
            for (int mt = 0; mt < 2; mt++)
#pragma unroll
                for (int nt = 0; nt < 4; nt++)
                    mma_bf16(oacc[mt][nt], af[mt], bl2[nt]);

#pragma unroll
            for (int mt = 0; mt < 2; mt++) {
                int r0 = warp_m * 32 + mt * 16 + g;
                af[mt][0] = pl[r0 * RSP + j0p + t];
                af[mt][1] = pl[(r0 + 8) * RSP + j0p + t];
                af[mt][2] = pl[r0 * RSP + j0p + 4 + t];
                af[mt][3] = pl[(r0 + 8) * RSP + j0p + 4 + t];
            }
#pragma unroll
            for (int mt = 0; mt < 2; mt++)
#pragma unroll
                for (int nt = 0; nt < 4; nt++)
                    mma_bf16(oacc[mt][nt], af[mt], bh2[nt]);
        }
    }

    // ---- epilogue: scatter O to original token order ----
#pragma unroll
    for (int mt = 0; mt < 2; mt++) {
        int q0 = warp_m * 32 + mt * 16 + g;
        int tok0 = sidx_sh[n * 64 + q0];
        int tok1 = sidx_sh[n * 64 + q0 + 8];
        size_t b0 = ((size_t)seg * S_DIM + tok0) * D_DIM;
        size_t b1 = ((size_t)seg * S_DIM + tok1) * D_DIM;
#pragma unroll
        for (int nt = 0; nt < 4; nt++) {
            int d0 = warp_n * 32 + nt * 8 + 2 * t;
            *(float2*)&g_oout[b0 + d0] = make_float2(oacc[mt][nt][0], oacc[mt][nt][1]);
            *(float2*)&g_oout[b1 + d0] = make_float2(oacc[mt][nt][2], oacc[mt][nt][3]);
        }
    }
}

// ------- combine rounds by softmax over lse; writes bf16 hi/lo directly ----
__global__ void combine_kernel()
{
    const int g = blockIdx.x * 256 + threadIdx.x;
    const int flat = g * 4;
    const int e = flat & (E_DIM - 1);
    const int sb = flat >> 10;
    const int b = sb & 1;
    const int s = sb >> 1;
    const int h = e >> 7;
    const int d = e & 127;

    const int seg0 = (b * R_DIM + 0) * H_DIM + h;
    const int seg1 = (b * R_DIM + 1) * H_DIM + h;

    float l0 = g_olse[(size_t)seg0 * S_DIM + s];
    float l1 = g_olse[(size_t)seg1 * S_DIM + s];
    float m = fmaxf(l0, l1);
    float e0 = __expf(l0 - m), e1 = __expf(l1 - m);
    float inv = 1.0f / (e0 + e1);
    float w0 = e0 * inv, w1 = e1 * inv;

    float4 o0 = *(const float4*)&g_oout[((size_t)seg0 * S_DIM + s) * D_DIM + d];
    float4 o1 = *(const float4*)&g_oout[((size_t)seg1 * S_DIM + s) * D_DIM + d];
    float4 r;
    r.x = w0 * o0.x + w1 * o1.x;
    r.y = w0 * o0.y + w1 * o1.y;
    r.z = w0 * o0.z + w1 * o1.z;
    r.w = w0 * o0.w + w1 * o1.w;
    uint2 hh, ll;
    split2(r.x, r.y, hh.x, ll.x);
    split2(r.z, r.w, hh.y, ll.y);
    ((uint2*)g_och)[g] = hh;
    ((uint2*)g_ocl)[g] = ll;
}

// ---------------- launcher ----------------
extern "C" void kernel_launch(void* const* d_in, const int* in_sizes, int n_in,
                              void* d_out, int out_size)
{
    const float* x      = (const float*)d_in[0];
    const float* wq     = (const float*)d_in[1];
    const float* bq     = (const float*)d_in[2];
    const float* wv     = (const float*)d_in[3];
    const float* bv     = (const float*)d_in[4];
    const float* wo     = (const float*)d_in[5];
    const float* bo     = (const float*)d_in[6];
    const float* hash_w = (const float*)d_in[7];
    float* out = (float*)d_out;

    float *p_qraw, *p_v;
    uint32_t *p_xh, *p_xl, *p_wvh, *p_wvl, *p_woh, *p_wol, *p_och, *p_ocl;
    cudaGetSymbolAddress((void**)&p_qraw, g_qraw);
    cudaGetSymbolAddress((void**)&p_v,    g_v);
    cudaGetSymbolAddress((void**)&p_xh,  g_xh);  cudaGetSymbolAddress((void**)&p_xl,  g_xl);
    cudaGetSymbolAddress((void**)&p_wvh, g_wvh); cudaGetSymbolAddress((void**)&p_wvl, g_wvl);
    cudaGetSymbolAddress((void**)&p_woh, g_woh); cudaGetSymbolAddress((void**)&p_wol, g_wol);
    cudaGetSymbolAddress((void**)&p_och, g_och); cudaGetSymbolAddress((void**)&p_ocl, g_ocl);

    cudaFuncSetAttribute(attn_kernel, cudaFuncAttributeMaxDynamicSharedMemorySize,
                         ATTN_SMEM);
    cudaFuncSetAttribute(gemm_bf16_kernel,
                         cudaFuncAttributeMaxDynamicSharedMemorySize, BGEMM_SMEM);

    dim3 gemm_grid(E_DIM / 128, MROWS / 128);
    const int nsplit = N4X + 2 * N4W;

    // pre-split x, wv, wo for bf16 GEMMs (one merged launch)
    split_all_kernel<<<(nsplit + 255) / 256, 256>>>((const float4*)x,
                                                    (const float4*)wv,
                                                    (const float4*)wo);
    // q: SIMT fp32 (flip-free); v: bf16 mma split (fp32 output)
    gemm_bias_kernel<<<gemm_grid, 256>>>(x, wq, bq, p_qraw, MROWS, E_DIM, E_DIM);
    gemm_bf16_kernel<<<gemm_grid, 256, BGEMM_SMEM>>>(p_xh, p_xl, p_wvh, p_wvl,
                                                     bv, p_v, MROWS, E_DIM, E_DIM);
    norm_split_kernel<<<MROWS, 256>>>();
    hash_kernel<<<dim3(S_DIM / 256, B_DIM * H_DIM), 256>>>(hash_w);
    sort_kernel<<<NSEG, 512>>>();
    attn_kernel<<<NSEG * NC_DIM, 256, ATTN_SMEM>>>();
    combine_kernel<<<MROWS * E_DIM / 4 / 256, 256>>>();
    gemm_bf16_kernel<<<gemm_grid, 256, BGEMM_SMEM>>>(p_och, p_ocl, p_woh, p_wol,
                                                     bo, out, MROWS, E_DIM, E_DIM);
}